// round 9
// baseline (speedup 1.0000x reference)
#include <cuda_runtime.h>
#include <cstdint>
#include <math.h>

#define N_NODES 10000
#define F_DIM   128
#define H_DIM   64
#define C_DIM   2
#define G_CNT   4
#define E_EDGES 320000
#define ET_EDGES (E_EDGES + N_NODES)   // 330000 with self loops
#define NPAD    10112                  // 79 * 128

// ---------------- scratch (device globals; no dynamic alloc) ----------------
__device__ float g_kf[F_DIM];
__device__ float g_ex[(size_t)NPAD * F_DIM];
__device__ float g_colinv[NPAD];
__device__ float g_h1[N_NODES * H_DIM];
__device__ float g_al[N_NODES], g_ar[N_NODES];
__device__ float g_al2[N_NODES], g_ar2[N_NODES];
__device__ float g_m[N_NODES], g_s[N_NODES];
__device__ float g_agg[N_NODES * H_DIM];
__device__ float g_h2[N_NODES * C_DIM];
__device__ float g_agg2[N_NODES * C_DIM];
__device__ float g_e[ET_EDGES];
__device__ float g_out_node[N_NODES];
__device__ float g_w2[NPAD];            // 2p-1
__device__ double g_t[N_NODES];         // row accumulators for norm
__device__ float g_loss[1];
__device__ float g_masksum[1];

// ---------------- helpers ----------------
__device__ __forceinline__ float wredsum(float v) {
    #pragma unroll
    for (int o = 16; o > 0; o >>= 1) v += __shfl_xor_sync(0xffffffffu, v, o);
    return v;
}

__device__ __forceinline__ void atomicMaxF(float* a, float v) {
    if (v >= 0.0f) atomicMax((int*)a, __float_as_int(v));
    else           atomicMin((unsigned int*)a, (unsigned int)__float_as_int(v));
}

__device__ __forceinline__ float sigmoidf_(float x) { return 1.0f / (1.0f + expf(-x)); }

// ---------------- k_init ----------------
__global__ void k_init(const float* __restrict__ logit_p,
                       const float* __restrict__ emb_w,
                       float* __restrict__ pw_out) {
    int f = threadIdx.x;
    if (f < F_DIM) {
        float p = sigmoidf_(logit_p[f]);
        pw_out[f] = 1.0f - p;
        const float EPSf = 2.2204460492503131e-16f;
        float approx = logf(p + EPSf) - logf(1.0f - p + EPSf);   // log(.5+eps) terms cancel
        float keep = 1.0f - sigmoidf_(approx * 10.0f);
        g_kf[f] = keep * sigmoidf_(emb_w[f]);
        if (f == 0) { g_loss[0] = 0.0f; g_masksum[0] = 0.0f; }
    }
}

// ---------------- k_ex: ex = x * kf (exact products), zero out_node, masksum ----------------
__global__ void k_ex(const float* __restrict__ x, const int* __restrict__ mask) {
    int w = blockIdx.x * 8 + (threadIdx.x >> 5);
    if (w >= NPAD) return;
    int lane = threadIdx.x & 31;
    if (w < N_NODES) {
        float4 kf = *(const float4*)&g_kf[lane * 4];
        float4 xv = *(const float4*)&x[(size_t)w * F_DIM + lane * 4];
        float4 e;
        e.x = __fmul_rn(xv.x, kf.x); e.y = __fmul_rn(xv.y, kf.y);
        e.z = __fmul_rn(xv.z, kf.z); e.w = __fmul_rn(xv.w, kf.w);
        *(float4*)&g_ex[(size_t)w * F_DIM + lane * 4] = e;
        if (lane == 0) {
            g_out_node[w] = 0.0f;
            if (mask[w] > 0) atomicAdd(&g_masksum[0], 1.0f);
        }
    } else {
        *(float4*)&g_ex[(size_t)w * F_DIM + lane * 4] = make_float4(0.f, 0.f, 0.f, 0.f);
    }
}

// ---------------- k_colinv: vec2 t-major row-reduction, per-iteration horizontal fold ----------------
// Thread t owns {2t, 2t+1} (iter 0) and {64+2t, 65+2t} (iter 1).
// Each iteration horizontally folds its vec2, then accumulates across iterations:
//   s_t = fl( fl(A+B) + fl(C+D) )
// then shfl warp tree (16,8,4,2,1). Products exact (kf=0.25); true IEEE division.
__global__ void k_colinv(const float* __restrict__ x) {
    int w = blockIdx.x * 8 + (threadIdx.x >> 5);   // row
    if (w >= NPAD) return;
    int lane = threadIdx.x & 31;
    if (w < N_NODES) {
        const float* xr = x + (size_t)w * F_DIM;
        float2 xa = *(const float2*)&xr[2 * lane];
        float2 xb = *(const float2*)&xr[2 * lane + 64];
        float2 ka = *(const float2*)&g_kf[2 * lane];
        float2 kb = *(const float2*)&g_kf[2 * lane + 64];
        float i0 = __fadd_rn(__fmul_rn(xa.x, ka.x), __fmul_rn(xa.y, ka.y));  // A+B
        float i1 = __fadd_rn(__fmul_rn(xb.x, kb.x), __fmul_rn(xb.y, kb.y));  // C+D
        float s = __fadd_rn(i0, i1);
        s = wredsum(s);
        if (lane == 0) g_colinv[w] = __fdiv_rn(1.0f, __fadd_rn(s, 1e-6f));
    } else if (lane == 0) {
        g_colinv[w] = 0.0f;
    }
}

// ---------------- k_h1 ----------------
__global__ void k_h1(const float* __restrict__ xin, const float* __restrict__ Wg,
                     const float* __restrict__ asrc, const float* __restrict__ adst) {
    int node = blockIdx.x * 8 + (threadIdx.x >> 5);
    if (node >= N_NODES) return;
    int lane = threadIdx.x & 31;
    const float* xr = xin + (size_t)node * F_DIM;
    float acc0 = 0.0f, acc1 = 0.0f;
    #pragma unroll 8
    for (int k = 0; k < F_DIM; k++) {
        float xa = __ldg(xr + k);
        acc0 = fmaf(xa, Wg[k * H_DIM + lane], acc0);
        acc1 = fmaf(xa, Wg[k * H_DIM + lane + 32], acc1);
    }
    g_h1[node * H_DIM + lane]      = acc0;
    g_h1[node * H_DIM + lane + 32] = acc1;
    float ap = wredsum(acc0 * asrc[lane] + acc1 * asrc[lane + 32]);
    float rp = wredsum(acc0 * adst[lane] + acc1 * adst[lane + 32]);
    if (lane == 0) { g_al[node] = ap; g_ar[node] = rp; g_m[node] = -INFINITY; g_s[node] = 0.0f; }
    g_agg[node * H_DIM + lane] = 0.0f;
    g_agg[node * H_DIM + lane + 32] = 0.0f;
}

// ---------------- edge pass A: e + segment max ----------------
__global__ void k_edge_max(const int* __restrict__ ei, int layer) {
    int idx = blockIdx.x * blockDim.x + threadIdx.x;
    if (idx >= ET_EDGES) return;
    int s, d;
    if (idx < E_EDGES) { s = ei[idx]; d = ei[E_EDGES + idx]; }
    else               { s = d = idx - E_EDGES; }
    const float* al = layer ? g_al2 : g_al;
    const float* ar = layer ? g_ar2 : g_ar;
    float v = al[s] + ar[d];
    v = (v >= 0.0f) ? v : 0.2f * v;
    g_e[idx] = v;
    atomicMaxF(&g_m[d], v);
}

// ---------------- edge pass B (layer1) ----------------
__global__ void k_edge_agg(const int* __restrict__ ei) {
    int w = blockIdx.x * 8 + (threadIdx.x >> 5);
    if (w >= ET_EDGES) return;
    int lane = threadIdx.x & 31;
    int s, d;
    if (w < E_EDGES) { s = ei[w]; d = ei[E_EDGES + w]; }
    else             { s = d = w - E_EDGES; }
    float ee;
    if (lane == 0) {
        ee = expf(g_e[w] - g_m[d]);
        atomicAdd(&g_s[d], ee);
    }
    ee = __shfl_sync(0xffffffffu, ee, 0);
    const float* hs = g_h1 + (size_t)s * H_DIM;
    float* ag = g_agg + (size_t)d * H_DIM;
    atomicAdd(ag + lane,      ee * hs[lane]);
    atomicAdd(ag + lane + 32, ee * hs[lane + 32]);
}

// ---------------- k_hid ----------------
__global__ void k_hid(const float* __restrict__ b1g, const float* __restrict__ gmg,
                      const float* __restrict__ btg, const float* __restrict__ W2g,
                      const float* __restrict__ as2, const float* __restrict__ ad2) {
    int node = blockIdx.x * 8 + (threadIdx.x >> 5);
    if (node >= N_NODES) return;
    int lane = threadIdx.x & 31;
    float inv = 1.0f / (g_s[node] + 1e-16f);
    float h0 = g_agg[node * H_DIM + lane] * inv + b1g[lane];
    float h1v = g_agg[node * H_DIM + lane + 32] * inv + b1g[lane + 32];
    const float BNS = 0.9999950000374997f;   // 1/sqrt(1+1e-5)
    h0  = h0  * gmg[lane]      * BNS + btg[lane];
    h1v = h1v * gmg[lane + 32] * BNS + btg[lane + 32];
    h0  = (h0  >= 0.0f) ? h0  : 0.01f * h0;
    h1v = (h1v >= 0.0f) ? h1v : 0.01f * h1v;
    float p0 = wredsum(h0 * W2g[lane * 2]     + h1v * W2g[(lane + 32) * 2]);
    float p1 = wredsum(h0 * W2g[lane * 2 + 1] + h1v * W2g[(lane + 32) * 2 + 1]);
    if (lane == 0) {
        g_h2[node * 2] = p0; g_h2[node * 2 + 1] = p1;
        g_al2[node] = p0 * as2[0] + p1 * as2[1];
        g_ar2[node] = p0 * ad2[0] + p1 * ad2[1];
        g_m[node] = -INFINITY; g_s[node] = 0.0f;
        g_agg2[node * 2] = 0.0f; g_agg2[node * 2 + 1] = 0.0f;
    }
}

// ---------------- edge pass B (layer2) ----------------
__global__ void k_edge_agg2(const int* __restrict__ ei) {
    int idx = blockIdx.x * blockDim.x + threadIdx.x;
    if (idx >= ET_EDGES) return;
    int s, d;
    if (idx < E_EDGES) { s = ei[idx]; d = ei[E_EDGES + idx]; }
    else               { s = d = idx - E_EDGES; }
    float ee = expf(g_e[idx] - g_m[d]);
    atomicAdd(&g_s[d], ee);
    atomicAdd(&g_agg2[d * 2],     ee * g_h2[s * 2]);
    atomicAdd(&g_agg2[d * 2 + 1], ee * g_h2[s * 2 + 1]);
}

// ---------------- k_out ----------------
__global__ void k_out(const float* __restrict__ b2g, const int* __restrict__ y,
                      const int* __restrict__ mask) {
    int i = blockIdx.x * blockDim.x + threadIdx.x;
    if (i >= N_NODES) return;
    float inv = 1.0f / (g_s[i] + 1e-16f);
    float o0 = g_agg2[i * 2] * inv + b2g[0];
    float o1 = g_agg2[i * 2 + 1] * inv + b2g[1];
    float mx = fmaxf(o0, o1);
    float lse = mx + logf(expf(o0 - mx) + expf(o1 - mx));
    float lp0 = o0 - lse, lp1 = o1 - lse;
    g_out_node[i] += expf(lp1);
    if (mask[i] > 0) atomicAdd(&g_loss[0], (y[i] == 0) ? lp0 : lp1);
}

// ---------------- k_nodep: node_p out, loss out, w2 = 2p-1, zero g_t ----------------
__global__ void k_nodep(float* __restrict__ dout) {
    int i = blockIdx.x * blockDim.x + threadIdx.x;
    if (i < NPAD) {
        if (i < N_NODES) {
            float p = g_out_node[i] * 0.25f;
            dout[i] = p;
            g_w2[i] = 2.0f * p - 1.0f;
            g_t[i] = 0.0;
        } else {
            g_w2[i] = 0.0f;
        }
    }
    if (i == 0) dout[N_NODES] = -g_loss[0] / (g_masksum[0] * (float)G_CNT);
}

// ---------------- k_graph: C[i,j] = dot(ex_i, ex_j) * colinv[j]; fused t_i accumulation ----------------
__global__ __launch_bounds__(256, 2) void k_graph(float* __restrict__ out) {
    __shared__ float2 Ap[16][66];    // (row r, row r+64) pairs
    __shared__ float2 Bd[16][130];   // duplicated B values
    int tid = threadIdx.x;
    int tx = tid & 15, ty = tid >> 4;
    int bi = blockIdx.y * 128, bj = blockIdx.x * 128;
    int lrow = tid >> 2;             // 0..63
    int lf4 = (tid & 3) * 4;         // 0,4,8,12

    unsigned long long c2[4][8];
    #pragma unroll
    for (int m = 0; m < 4; m++)
        #pragma unroll
        for (int n = 0; n < 8; n++) c2[m][n] = 0ull;

    const float* exA0 = g_ex + (size_t)(bi + lrow) * F_DIM + lf4;
    const float* exA1 = exA0 + (size_t)64 * F_DIM;
    const float* exB0 = g_ex + (size_t)(bj + lrow) * F_DIM + lf4;
    const float* exB1 = exB0 + (size_t)64 * F_DIM;

    for (int k0 = 0; k0 < F_DIM; k0 += 16) {
        float4 a0 = *(const float4*)(exA0 + k0);
        float4 a1 = *(const float4*)(exA1 + k0);
        float4 b0 = *(const float4*)(exB0 + k0);
        float4 b1 = *(const float4*)(exB1 + k0);
        __syncthreads();
        Ap[lf4 + 0][lrow] = make_float2(a0.x, a1.x);
        Ap[lf4 + 1][lrow] = make_float2(a0.y, a1.y);
        Ap[lf4 + 2][lrow] = make_float2(a0.z, a1.z);
        Ap[lf4 + 3][lrow] = make_float2(a0.w, a1.w);
        Bd[lf4 + 0][lrow] = make_float2(b0.x, b0.x);
        Bd[lf4 + 1][lrow] = make_float2(b0.y, b0.y);
        Bd[lf4 + 2][lrow] = make_float2(b0.z, b0.z);
        Bd[lf4 + 3][lrow] = make_float2(b0.w, b0.w);
        Bd[lf4 + 0][lrow + 64] = make_float2(b1.x, b1.x);
        Bd[lf4 + 1][lrow + 64] = make_float2(b1.y, b1.y);
        Bd[lf4 + 2][lrow + 64] = make_float2(b1.z, b1.z);
        Bd[lf4 + 3][lrow + 64] = make_float2(b1.w, b1.w);
        __syncthreads();
        #pragma unroll
        for (int k = 0; k < 16; k++) {
            unsigned long long av[4], bv[8];
            #pragma unroll
            for (int m = 0; m < 4; m++)
                av[m] = *reinterpret_cast<const unsigned long long*>(&Ap[k][ty + 16 * m]);
            #pragma unroll
            for (int n = 0; n < 8; n++)
                bv[n] = *reinterpret_cast<const unsigned long long*>(&Bd[k][tx + 16 * n]);
            #pragma unroll
            for (int m = 0; m < 4; m++)
                #pragma unroll
                for (int n = 0; n < 8; n++)
                    asm("fma.rn.f32x2 %0, %1, %2, %0;"
                        : "+l"(c2[m][n]) : "l"(av[m]), "l"(bv[n]));
        }
    }

    // Epilogue: store graph values AND accumulate t_i = sum_j graph[i,j] * (2p_j-1)
    float acc_lo[4] = {0.f, 0.f, 0.f, 0.f};
    float acc_hi[4] = {0.f, 0.f, 0.f, 0.f};
    #pragma unroll
    for (int n = 0; n < 8; n++) {
        int cj = bj + tx + 16 * n;
        if (cj >= N_NODES) continue;
        float ci = g_colinv[cj];
        float wj = g_w2[cj];
        #pragma unroll
        for (int m = 0; m < 4; m++) {
            int r0 = bi + ty + 16 * m;
            unsigned long long v = c2[m][n];
            float lo = __fmul_rn(__uint_as_float((unsigned)(v & 0xffffffffull)), ci);
            float hi = __fmul_rn(__uint_as_float((unsigned)(v >> 32)), ci);
            if (r0 < N_NODES) {
                out[(size_t)r0 * N_NODES + cj] = lo;
                acc_lo[m] = fmaf(lo, wj, acc_lo[m]);
            }
            if (r0 + 64 < N_NODES) {
                out[(size_t)(r0 + 64) * N_NODES + cj] = hi;
                acc_hi[m] = fmaf(hi, wj, acc_hi[m]);
            }
        }
    }
    #pragma unroll
    for (int m = 0; m < 4; m++) {
        #pragma unroll
        for (int o = 8; o > 0; o >>= 1) {
            acc_lo[m] += __shfl_xor_sync(0xffffffffu, acc_lo[m], o);
            acc_hi[m] += __shfl_xor_sync(0xffffffffu, acc_hi[m], o);
        }
        if (tx == 0) {
            int r0 = bi + ty + 16 * m;
            if (r0 < N_NODES)      atomicAdd(&g_t[r0],      (double)acc_lo[m]);
            if (r0 + 64 < N_NODES) atomicAdd(&g_t[r0 + 64], (double)acc_hi[m]);
        }
    }
}

// ---------------- k_normf: norm[:,1] = sigmoid(t_i) ----------------
__global__ void k_normf(float* __restrict__ outp) {
    int i = blockIdx.x * blockDim.x + threadIdx.x;
    if (i >= N_NODES) return;
    float t = (float)g_t[i];
    outp[i] = 1.0f / (1.0f + expf(-t));
}

// ---------------- launch ----------------
extern "C" void kernel_launch(void* const* d_in, const int* in_sizes, int n_in,
                              void* d_out, int out_size) {
    const float* x      = (const float*)d_in[0];
    const int*   y      = (const int*)d_in[1];
    const int*   mask   = (const int*)d_in[2];
    const int*   e_ppi  = (const int*)d_in[3];
    const int*   e_hom  = (const int*)d_in[4];
    const float* W1     = (const float*)d_in[5];
    const float* as1    = (const float*)d_in[6];
    const float* ad1    = (const float*)d_in[7];
    const float* b1     = (const float*)d_in[8];
    const float* gamma_ = (const float*)d_in[9];
    const float* beta_  = (const float*)d_in[10];
    const float* W2     = (const float*)d_in[11];
    const float* as2    = (const float*)d_in[12];
    const float* ad2    = (const float*)d_in[13];
    const float* b2     = (const float*)d_in[14];
    const float* emb_w  = (const float*)d_in[15];
    const float* logitp = (const float*)d_in[16];
    float* out = (float*)d_out;

    const size_t OFF_NORM  = (size_t)N_NODES + 1;
    const size_t OFF_GRAPH = (size_t)2 * N_NODES + 1;
    const size_t OFF_PW    = OFF_GRAPH + (size_t)N_NODES * N_NODES;

    k_init<<<1, 128>>>(logitp, emb_w, out + OFF_PW);
    k_ex<<<NPAD / 8, 256>>>(x, mask);
    k_colinv<<<NPAD / 8, 256>>>(x);

    for (int g = 0; g < G_CNT; g++) {
        const int* ei = (g % 2 == 0) ? e_ppi : e_hom;
        k_h1<<<1250, 256>>>(x, W1 + g * F_DIM * H_DIM, as1 + g * H_DIM, ad1 + g * H_DIM);
        k_edge_max<<<(ET_EDGES + 255) / 256, 256>>>(ei, 0);
        k_edge_agg<<<(ET_EDGES + 7) / 8, 256>>>(ei);
        k_hid<<<1250, 256>>>(b1 + g * H_DIM, gamma_ + g * H_DIM, beta_ + g * H_DIM,
                             W2 + g * H_DIM * C_DIM, as2 + g * C_DIM, ad2 + g * C_DIM);
        k_edge_max<<<(ET_EDGES + 255) / 256, 256>>>(ei, 1);
        k_edge_agg2<<<(ET_EDGES + 255) / 256, 256>>>(ei);
        k_out<<<(N_NODES + 255) / 256, 256>>>(b2 + g * C_DIM, y, mask);
    }

    k_nodep<<<(NPAD + 255) / 256, 256>>>(out);
    dim3 gg(79, 79);
    k_graph<<<gg, 256>>>(out + OFF_GRAPH);
    k_normf<<<(N_NODES + 255) / 256, 256>>>(out + OFF_NORM);
}

// round 10
// speedup vs baseline: 1.4850x; 1.4850x over previous
#include <cuda_runtime.h>
#include <cstdint>
#include <math.h>

#define N_NODES 10000
#define F_DIM   128
#define H_DIM   64
#define C_DIM   2
#define G_CNT   4
#define E_EDGES 320000
#define NPAD    10112                  // 79 * 128

// ---------------- scratch (device globals; no dynamic alloc) ----------------
__device__ float  g_kf[F_DIM];
__device__ float  g_ex[(size_t)NPAD * F_DIM];
__device__ float  g_colinv[NPAD];
__device__ float2 g_W1p[G_CNT * F_DIM * 32];               // packed (c, c+32) pairs
__device__ float2 g_h1p[(size_t)G_CNT * N_NODES * 32];     // packed h1
__device__ float  g_al4[G_CNT * N_NODES], g_ar4[G_CNT * N_NODES];
__device__ float  g_al2a[G_CNT * N_NODES], g_ar2a[G_CNT * N_NODES];
__device__ float2 g_h2a[G_CNT * N_NODES];
__device__ float  g_oacc[G_CNT][N_NODES];
__device__ int    g_cnt[2][NPAD];
__device__ int    g_off[2][NPAD];
__device__ int    g_cur[2][NPAD];
__device__ int    g_csr[2][E_EDGES];
__device__ float  g_w2[NPAD];            // 2p-1 (zero padded)
__device__ double g_t[N_NODES];          // row accumulators for norm
__device__ float  g_loss[1];
__device__ float  g_masksum[1];

// ---------------- helpers ----------------
__device__ __forceinline__ float wredsum(float v) {
    #pragma unroll
    for (int o = 16; o > 0; o >>= 1) v += __shfl_xor_sync(0xffffffffu, v, o);
    return v;
}
__device__ __forceinline__ float sigmoidf_(float x) { return 1.0f / (1.0f + expf(-x)); }

// ---------------- k_init ----------------
__global__ void k_init(const float* __restrict__ logit_p,
                       const float* __restrict__ emb_w,
                       float* __restrict__ pw_out) {
    int f = threadIdx.x;
    if (f < F_DIM) {
        float p = sigmoidf_(logit_p[f]);
        pw_out[f] = 1.0f - p;
        const float EPSf = 2.2204460492503131e-16f;
        float approx = logf(p + EPSf) - logf(1.0f - p + EPSf);
        float keep = 1.0f - sigmoidf_(approx * 10.0f);
        g_kf[f] = keep * sigmoidf_(emb_w[f]);
        if (f == 0) { g_loss[0] = 0.0f; g_masksum[0] = 0.0f; }
    }
}

// ---------------- k_prep: pack W1 into (c, c+32) float2 pairs ----------------
__global__ void k_prep(const float* __restrict__ W1) {
    int idx = blockIdx.x * 256 + threadIdx.x;      // g*F*32 entries
    if (idx >= G_CNT * F_DIM * 32) return;
    int lane = idx & 31;
    int k = (idx >> 5) & 127;
    int g = idx >> 12;
    const float* Wg = W1 + g * F_DIM * H_DIM + k * H_DIM;
    g_W1p[idx] = make_float2(Wg[lane], Wg[lane + 32]);
}

// ---------------- k_ex: ex = x * kf (exact products), masksum, zero csr counts ----------------
__global__ void k_ex(const float* __restrict__ x, const int* __restrict__ mask) {
    int w = blockIdx.x * 8 + (threadIdx.x >> 5);
    if (w >= NPAD) return;
    int lane = threadIdx.x & 31;
    if (w < N_NODES) {
        float4 kf = *(const float4*)&g_kf[lane * 4];
        float4 xv = *(const float4*)&x[(size_t)w * F_DIM + lane * 4];
        float4 e;
        e.x = __fmul_rn(xv.x, kf.x); e.y = __fmul_rn(xv.y, kf.y);
        e.z = __fmul_rn(xv.z, kf.z); e.w = __fmul_rn(xv.w, kf.w);
        *(float4*)&g_ex[(size_t)w * F_DIM + lane * 4] = e;
        if (lane == 0 && mask[w] > 0) atomicAdd(&g_masksum[0], 1.0f);
    } else {
        *(float4*)&g_ex[(size_t)w * F_DIM + lane * 4] = make_float4(0.f, 0.f, 0.f, 0.f);
    }
    if (lane == 1) { g_cnt[0][w] = 0; g_cnt[1][w] = 0; }
}

// ---------------- k_colinv: SACRED — matched reference emitter order; do not touch ----------------
__global__ void k_colinv(const float* __restrict__ x) {
    int w = blockIdx.x * 8 + (threadIdx.x >> 5);
    if (w >= NPAD) return;
    int lane = threadIdx.x & 31;
    if (w < N_NODES) {
        const float* xr = x + (size_t)w * F_DIM;
        float2 xa = *(const float2*)&xr[2 * lane];
        float2 xb = *(const float2*)&xr[2 * lane + 64];
        float2 ka = *(const float2*)&g_kf[2 * lane];
        float2 kb = *(const float2*)&g_kf[2 * lane + 64];
        float i0 = __fadd_rn(__fmul_rn(xa.x, ka.x), __fmul_rn(xa.y, ka.y));
        float i1 = __fadd_rn(__fmul_rn(xb.x, kb.x), __fmul_rn(xb.y, kb.y));
        float s = __fadd_rn(i0, i1);
        s = wredsum(s);
        if (lane == 0) g_colinv[w] = __fdiv_rn(1.0f, __fadd_rn(s, 1e-6f));
    } else if (lane == 0) {
        g_colinv[w] = 0.0f;
    }
}

// ---------------- CSR build ----------------
__global__ void k_csr_hist(const int* __restrict__ e0, const int* __restrict__ e1) {
    int idx = blockIdx.x * 256 + threadIdx.x;
    if (idx >= E_EDGES) return;
    const int* ei = blockIdx.y ? e1 : e0;
    atomicAdd(&g_cnt[blockIdx.y][ei[E_EDGES + idx]], 1);
}

__global__ void k_csr_scan() {
    __shared__ int part[1024];
    int t = threadIdx.x;
    for (int list = 0; list < 2; list++) {
        const int chunk = 10;
        int base = t * chunk;
        int sum = 0;
        #pragma unroll
        for (int i = 0; i < chunk; i++) {
            int idx = base + i;
            if (idx < N_NODES) sum += g_cnt[list][idx];
        }
        part[t] = sum;
        __syncthreads();
        for (int off = 1; off < 1024; off <<= 1) {
            int u = (t >= off) ? part[t - off] : 0;
            __syncthreads();
            part[t] += u;
            __syncthreads();
        }
        int run = part[t] - sum;   // exclusive prefix
        for (int i = 0; i < chunk; i++) {
            int idx = base + i;
            if (idx < N_NODES) {
                g_off[list][idx] = run;
                g_cur[list][idx] = run;
                run += g_cnt[list][idx];
            }
        }
        __syncthreads();
    }
}

__global__ void k_csr_scatter(const int* __restrict__ e0, const int* __restrict__ e1) {
    int idx = blockIdx.x * 256 + threadIdx.x;
    if (idx >= E_EDGES) return;
    int list = blockIdx.y;
    const int* ei = list ? e1 : e0;
    int s = ei[idx], d = ei[E_EDGES + idx];
    int pos = atomicAdd(&g_cur[list][d], 1);
    g_csr[list][pos] = s;
}

// ---------------- k_h1_all: h1 = x @ W1[g] for all 4 graphs (FFMA2), al/ar ----------------
__global__ __launch_bounds__(256) void k_h1_all(const float* __restrict__ x,
                                                const float* __restrict__ as1,
                                                const float* __restrict__ ad1) {
    int warp = blockIdx.x * 8 + (threadIdx.x >> 5);
    int lane = threadIdx.x & 31;
    if (warp >= 2500) return;
    int n0 = warp * 4;

    unsigned long long acc[4][4];
    #pragma unroll
    for (int g = 0; g < 4; g++)
        #pragma unroll
        for (int nd = 0; nd < 4; nd++) acc[g][nd] = 0ull;

    const float* xr = x + (size_t)n0 * F_DIM;
    for (int k = 0; k < F_DIM; k++) {
        unsigned long long xd[4];
        #pragma unroll
        for (int nd = 0; nd < 4; nd++) {
            unsigned xu = __float_as_uint(__ldg(xr + nd * F_DIM + k));
            asm("mov.b64 %0, {%1, %1};" : "=l"(xd[nd]) : "r"(xu));
        }
        #pragma unroll
        for (int g = 0; g < 4; g++) {
            float2 wv = g_W1p[(g * F_DIM + k) * 32 + lane];
            unsigned long long wd = *reinterpret_cast<unsigned long long*>(&wv);
            #pragma unroll
            for (int nd = 0; nd < 4; nd++)
                asm("fma.rn.f32x2 %0, %1, %2, %0;"
                    : "+l"(acc[g][nd]) : "l"(xd[nd]), "l"(wd));
        }
    }
    #pragma unroll
    for (int g = 0; g < 4; g++) {
        float asl = as1[g * 64 + lane], ash = as1[g * 64 + lane + 32];
        float adl = ad1[g * 64 + lane], adh = ad1[g * 64 + lane + 32];
        #pragma unroll
        for (int nd = 0; nd < 4; nd++) {
            unsigned long long v = acc[g][nd];
            float lo = __uint_as_float((unsigned)(v & 0xffffffffull));
            float hi = __uint_as_float((unsigned)(v >> 32));
            g_h1p[((size_t)g * N_NODES + n0 + nd) * 32 + lane] = make_float2(lo, hi);
            float ap = wredsum(lo * asl + hi * ash);
            float rp = wredsum(lo * adl + hi * adh);
            if (lane == 0) {
                g_al4[g * N_NODES + n0 + nd] = ap;
                g_ar4[g * N_NODES + n0 + nd] = rp;
            }
        }
    }
}

// ---------------- k_gat1_all: layer-1 GAT (no max pass, CSR, fused hid/h2) ----------------
__global__ void k_gat1_all(const float* __restrict__ b1, const float* __restrict__ gm,
                           const float* __restrict__ bt, const float* __restrict__ W2,
                           const float* __restrict__ as2, const float* __restrict__ ad2) {
    int g = blockIdx.y, list = g & 1;
    int d = blockIdx.x * 8 + (threadIdx.x >> 5);
    if (d >= N_NODES) return;
    int lane = threadIdx.x & 31;

    const float* al = g_al4 + g * N_NODES;
    float ard = g_ar4[g * N_NODES + d];
    const float2* h1p = g_h1p + (size_t)g * N_NODES * 32;

    // self loop
    float a0 = al[d] + ard; a0 = (a0 >= 0.f) ? a0 : 0.2f * a0;
    float ee = expf(a0);
    float2 hd = h1p[d * 32 + lane];
    float accx = ee * hd.x, accy = ee * hd.y, s = ee;

    int k1 = g_off[list][d] + g_cnt[list][d];
    for (int k = g_off[list][d]; k < k1; k++) {
        int src = g_csr[list][k];
        float a = al[src] + ard; a = (a >= 0.f) ? a : 0.2f * a;
        float e = expf(a);
        float2 h = h1p[src * 32 + lane];
        s += e;
        accx = fmaf(e, h.x, accx);
        accy = fmaf(e, h.y, accy);
    }
    float inv = 1.0f / (s + 1e-16f);
    float h0  = accx * inv + b1[g * 64 + lane];
    float h1v = accy * inv + b1[g * 64 + lane + 32];
    const float BNS = 0.9999950000374997f;   // 1/sqrt(1+1e-5)
    h0  = h0  * gm[g * 64 + lane]      * BNS + bt[g * 64 + lane];
    h1v = h1v * gm[g * 64 + lane + 32] * BNS + bt[g * 64 + lane + 32];
    h0  = (h0  >= 0.f) ? h0  : 0.01f * h0;
    h1v = (h1v >= 0.f) ? h1v : 0.01f * h1v;
    const float* W2g = W2 + g * H_DIM * C_DIM;
    float p0 = wredsum(h0 * W2g[lane * 2]     + h1v * W2g[(lane + 32) * 2]);
    float p1 = wredsum(h0 * W2g[lane * 2 + 1] + h1v * W2g[(lane + 32) * 2 + 1]);
    if (lane == 0) {
        g_h2a[g * N_NODES + d] = make_float2(p0, p1);
        g_al2a[g * N_NODES + d] = p0 * as2[g * 2] + p1 * as2[g * 2 + 1];
        g_ar2a[g * N_NODES + d] = p0 * ad2[g * 2] + p1 * ad2[g * 2 + 1];
    }
}

// ---------------- k_gat2_all: layer-2 GAT + log_softmax + loss (fused k_out) ----------------
__global__ void k_gat2_all(const float* __restrict__ b2, const int* __restrict__ y,
                           const int* __restrict__ mask) {
    int g = blockIdx.y, list = g & 1;
    int d = blockIdx.x * 8 + (threadIdx.x >> 5);
    if (d >= N_NODES) return;
    int lane = threadIdx.x & 31;

    const float* al2 = g_al2a + g * N_NODES;
    float ar2d = g_ar2a[g * N_NODES + d];
    const float2* h2 = g_h2a + g * N_NODES;

    float s = 0.f, o0 = 0.f, o1 = 0.f;
    int k0 = g_off[list][d], k1 = k0 + g_cnt[list][d];
    for (int k = k0 + lane; k < k1; k += 32) {
        int src = g_csr[list][k];
        float a = al2[src] + ar2d; a = (a >= 0.f) ? a : 0.2f * a;
        float e = expf(a);
        float2 h = h2[src];
        s += e;
        o0 = fmaf(e, h.x, o0);
        o1 = fmaf(e, h.y, o1);
    }
    s = wredsum(s); o0 = wredsum(o0); o1 = wredsum(o1);
    if (lane == 0) {
        float a = al2[d] + ar2d; a = (a >= 0.f) ? a : 0.2f * a;
        float es = expf(a);
        float2 hd = h2[d];
        s += es; o0 += es * hd.x; o1 += es * hd.y;
        float inv = 1.0f / (s + 1e-16f);
        float v0 = o0 * inv + b2[g * 2];
        float v1 = o1 * inv + b2[g * 2 + 1];
        float mx = fmaxf(v0, v1);
        float lse = mx + logf(expf(v0 - mx) + expf(v1 - mx));
        float lp0 = v0 - lse, lp1 = v1 - lse;
        g_oacc[g][d] = expf(lp1);
        if (mask[d] > 0) atomicAdd(&g_loss[0], (y[d] == 0) ? lp0 : lp1);
    }
}

// ---------------- k_nodep: node_p out, loss out, w2 = 2p-1, zero g_t ----------------
__global__ void k_nodep(float* __restrict__ dout) {
    int i = blockIdx.x * blockDim.x + threadIdx.x;
    if (i < NPAD) {
        if (i < N_NODES) {
            float p = (((g_oacc[0][i] + g_oacc[1][i]) + g_oacc[2][i]) + g_oacc[3][i]) * 0.25f;
            dout[i] = p;
            g_w2[i] = 2.0f * p - 1.0f;
            g_t[i] = 0.0;
        } else {
            g_w2[i] = 0.0f;
        }
    }
    if (i == 0) dout[N_NODES] = -g_loss[0] / (g_masksum[0] * (float)G_CNT);
}

// ---------------- k_graph: triangular tiles; direct + transposed emission; fused t ----------------
__global__ __launch_bounds__(256, 2) void k_graph(float* __restrict__ out) {
    __shared__ float2 Ap[16][66];
    __shared__ float2 Bd[16][130];
    __shared__ float  Tt[16][132];
    int tid = threadIdx.x;
    int tx = tid & 15, ty = tid >> 4;
    int bib = blockIdx.y, bjb = blockIdx.x;
    if (bjb < bib) return;                    // triangle only
    int bi = bib * 128, bj = bjb * 128;
    int lrow = tid >> 2;
    int lf4 = (tid & 3) * 4;

    unsigned long long c2[4][8];
    #pragma unroll
    for (int m = 0; m < 4; m++)
        #pragma unroll
        for (int n = 0; n < 8; n++) c2[m][n] = 0ull;

    const float* exA0 = g_ex + (size_t)(bi + lrow) * F_DIM + lf4;
    const float* exA1 = exA0 + (size_t)64 * F_DIM;
    const float* exB0 = g_ex + (size_t)(bj + lrow) * F_DIM + lf4;
    const float* exB1 = exB0 + (size_t)64 * F_DIM;

    for (int k0 = 0; k0 < F_DIM; k0 += 16) {
        float4 a0 = *(const float4*)(exA0 + k0);
        float4 a1 = *(const float4*)(exA1 + k0);
        float4 b0 = *(const float4*)(exB0 + k0);
        float4 b1 = *(const float4*)(exB1 + k0);
        __syncthreads();
        Ap[lf4 + 0][lrow] = make_float2(a0.x, a1.x);
        Ap[lf4 + 1][lrow] = make_float2(a0.y, a1.y);
        Ap[lf4 + 2][lrow] = make_float2(a0.z, a1.z);
        Ap[lf4 + 3][lrow] = make_float2(a0.w, a1.w);
        Bd[lf4 + 0][lrow] = make_float2(b0.x, b0.x);
        Bd[lf4 + 1][lrow] = make_float2(b0.y, b0.y);
        Bd[lf4 + 2][lrow] = make_float2(b0.z, b0.z);
        Bd[lf4 + 3][lrow] = make_float2(b0.w, b0.w);
        Bd[lf4 + 0][lrow + 64] = make_float2(b1.x, b1.x);
        Bd[lf4 + 1][lrow + 64] = make_float2(b1.y, b1.y);
        Bd[lf4 + 2][lrow + 64] = make_float2(b1.z, b1.z);
        Bd[lf4 + 3][lrow + 64] = make_float2(b1.w, b1.w);
        __syncthreads();
        #pragma unroll
        for (int k = 0; k < 16; k++) {
            unsigned long long av[4], bv[8];
            #pragma unroll
            for (int m = 0; m < 4; m++)
                av[m] = *reinterpret_cast<const unsigned long long*>(&Ap[k][ty + 16 * m]);
            #pragma unroll
            for (int n = 0; n < 8; n++)
                bv[n] = *reinterpret_cast<const unsigned long long*>(&Bd[k][tx + 16 * n]);
            #pragma unroll
            for (int m = 0; m < 4; m++)
                #pragma unroll
                for (int n = 0; n < 8; n++)
                    asm("fma.rn.f32x2 %0, %1, %2, %0;"
                        : "+l"(c2[m][n]) : "l"(av[m]), "l"(bv[n]));
        }
    }

    // ---- direct emission: C[i,j] = d * colinv[j], rows i in bi-block ----
    {
        float acc_lo[4] = {0.f, 0.f, 0.f, 0.f};
        float acc_hi[4] = {0.f, 0.f, 0.f, 0.f};
        #pragma unroll
        for (int n = 0; n < 8; n++) {
            int cj = bj + tx + 16 * n;
            if (cj >= N_NODES) continue;
            float ci = g_colinv[cj];
            float wj = g_w2[cj];
            #pragma unroll
            for (int m = 0; m < 4; m++) {
                int r0 = bi + ty + 16 * m;
                unsigned long long v = c2[m][n];
                float lo = __fmul_rn(__uint_as_float((unsigned)(v & 0xffffffffull)), ci);
                float hi = __fmul_rn(__uint_as_float((unsigned)(v >> 32)), ci);
                if (r0 < N_NODES) {
                    out[(size_t)r0 * N_NODES + cj] = lo;
                    acc_lo[m] = fmaf(lo, wj, acc_lo[m]);
                }
                if (r0 + 64 < N_NODES) {
                    out[(size_t)(r0 + 64) * N_NODES + cj] = hi;
                    acc_hi[m] = fmaf(hi, wj, acc_hi[m]);
                }
            }
        }
        #pragma unroll
        for (int m = 0; m < 4; m++) {
            #pragma unroll
            for (int o = 8; o > 0; o >>= 1) {
                acc_lo[m] += __shfl_xor_sync(0xffffffffu, acc_lo[m], o);
                acc_hi[m] += __shfl_xor_sync(0xffffffffu, acc_hi[m], o);
            }
            if (tx == 0) {
                int r0 = bi + ty + 16 * m;
                if (r0 < N_NODES)      atomicAdd(&g_t[r0],      (double)acc_lo[m]);
                if (r0 + 64 < N_NODES) atomicAdd(&g_t[r0 + 64], (double)acc_hi[m]);
            }
        }
    }

    // ---- transposed emission (off-diagonal tiles): C[j,i] = d * colinv[i] ----
    if (bib != bjb) {
        int warp = tid >> 5;
        int lane = tid & 31;
        #pragma unroll 1
        for (int n = 0; n < 8; n++) {
            __syncthreads();
            #pragma unroll
            for (int m = 0; m < 4; m++) {
                unsigned long long v = c2[m][n];
                Tt[tx][ty + 16 * m]      = __uint_as_float((unsigned)(v & 0xffffffffull));
                Tt[tx][ty + 16 * m + 64] = __uint_as_float((unsigned)(v >> 32));
            }
            __syncthreads();
            #pragma unroll
            for (int rr = 0; rr < 2; rr++) {
                int jloc = warp * 2 + rr;
                int cg = bj + 16 * n + jloc;       // output row (uniform per warp)
                float tacc = 0.f;
                if (cg < N_NODES) {
                    float4 tv = *(float4*)&Tt[jloc][lane * 4];
                    int r0 = bi + lane * 4;        // output cols
                    float4 civ = *(const float4*)&g_colinv[r0];
                    float4 wv  = *(const float4*)&g_w2[r0];
                    float v0 = __fmul_rn(tv.x, civ.x);
                    float v1 = __fmul_rn(tv.y, civ.y);
                    float v2 = __fmul_rn(tv.z, civ.z);
                    float v3 = __fmul_rn(tv.w, civ.w);
                    size_t rowb = (size_t)cg * N_NODES;
                    if (r0 + 3 < N_NODES) {
                        out[rowb + r0]     = v0;
                        out[rowb + r0 + 1] = v1;
                        out[rowb + r0 + 2] = v2;
                        out[rowb + r0 + 3] = v3;
                    } else {
                        if (r0     < N_NODES) out[rowb + r0]     = v0;
                        if (r0 + 1 < N_NODES) out[rowb + r0 + 1] = v1;
                        if (r0 + 2 < N_NODES) out[rowb + r0 + 2] = v2;
                        if (r0 + 3 < N_NODES) out[rowb + r0 + 3] = v3;
                    }
                    tacc = v0 * wv.x + v1 * wv.y + v2 * wv.z + v3 * wv.w;
                }
                #pragma unroll
                for (int o = 16; o > 0; o >>= 1)
                    tacc += __shfl_xor_sync(0xffffffffu, tacc, o);
                if (lane == 0 && cg < N_NODES)
                    atomicAdd(&g_t[cg], (double)tacc);
            }
        }
    }
}

// ---------------- k_normf: norm[:,1] = sigmoid(t_i) ----------------
__global__ void k_normf(float* __restrict__ outp) {
    int i = blockIdx.x * blockDim.x + threadIdx.x;
    if (i >= N_NODES) return;
    float t = (float)g_t[i];
    outp[i] = 1.0f / (1.0f + expf(-t));
}

// ---------------- launch ----------------
extern "C" void kernel_launch(void* const* d_in, const int* in_sizes, int n_in,
                              void* d_out, int out_size) {
    const float* x      = (const float*)d_in[0];
    const int*   y      = (const int*)d_in[1];
    const int*   mask   = (const int*)d_in[2];
    const int*   e_ppi  = (const int*)d_in[3];
    const int*   e_hom  = (const int*)d_in[4];
    const float* W1     = (const float*)d_in[5];
    const float* as1    = (const float*)d_in[6];
    const float* ad1    = (const float*)d_in[7];
    const float* b1     = (const float*)d_in[8];
    const float* gamma_ = (const float*)d_in[9];
    const float* beta_  = (const float*)d_in[10];
    const float* W2     = (const float*)d_in[11];
    const float* as2    = (const float*)d_in[12];
    const float* ad2    = (const float*)d_in[13];
    const float* b2     = (const float*)d_in[14];
    const float* emb_w  = (const float*)d_in[15];
    const float* logitp = (const float*)d_in[16];
    float* out = (float*)d_out;

    const size_t OFF_NORM  = (size_t)N_NODES + 1;
    const size_t OFF_GRAPH = (size_t)2 * N_NODES + 1;
    const size_t OFF_PW    = OFF_GRAPH + (size_t)N_NODES * N_NODES;

    k_init<<<1, 128>>>(logitp, emb_w, out + OFF_PW);
    k_prep<<<(G_CNT * F_DIM * 32 + 255) / 256, 256>>>(W1);
    k_ex<<<NPAD / 8, 256>>>(x, mask);
    k_colinv<<<NPAD / 8, 256>>>(x);

    dim3 eg((E_EDGES + 255) / 256, 2);
    k_csr_hist<<<eg, 256>>>(e_ppi, e_hom);
    k_csr_scan<<<1, 1024>>>();
    k_csr_scatter<<<eg, 256>>>(e_ppi, e_hom);

    k_h1_all<<<313, 256>>>(x, as1, ad1);

    dim3 gg1(1250, G_CNT);
    k_gat1_all<<<gg1, 256>>>(b1, gamma_, beta_, W2, as2, ad2);
    k_gat2_all<<<gg1, 256>>>(b2, y, mask);

    k_nodep<<<(NPAD + 255) / 256, 256>>>(out);
    dim3 ggr(79, 79);
    k_graph<<<ggr, 256>>>(out + OFF_GRAPH);
    k_normf<<<(N_NODES + 255) / 256, 256>>>(out + OFF_NORM);
}

// round 12
// speedup vs baseline: 1.9747x; 1.3297x over previous
#include <cuda_runtime.h>
#include <cuda_bf16.h>
#include <cstdint>
#include <math.h>

#define N_NODES 10000
#define F_DIM   128
#define H_DIM   64
#define C_DIM   2
#define G_CNT   4
#define E_EDGES 320000
#define NPAD    10112                  // 79 * 128

// ---------------- scratch (device globals; no dynamic alloc) ----------------
__device__ float  g_kf[F_DIM];
__device__ float  g_ex[(size_t)NPAD * F_DIM];
__device__ __align__(16) __nv_bfloat16 g_exs[3][(size_t)NPAD * F_DIM];  // hi/mid/lo splits
__device__ float  g_colinv[NPAD];
__device__ float2 g_W1p[G_CNT * F_DIM * 32];               // packed (c, c+32) pairs
__device__ float2 g_h1p[(size_t)G_CNT * N_NODES * 32];     // packed h1
__device__ float  g_al4[G_CNT * N_NODES], g_ar4[G_CNT * N_NODES];
__device__ float  g_al2a[G_CNT * N_NODES], g_ar2a[G_CNT * N_NODES];
__device__ float2 g_h2a[G_CNT * N_NODES];
__device__ float  g_oacc[G_CNT][N_NODES];
__device__ int    g_cnt[2][NPAD];
__device__ int    g_off[2][NPAD];
__device__ int    g_cur[2][NPAD];
__device__ int    g_csr[2][E_EDGES];
__device__ float  g_w2[NPAD];            // 2p-1 (zero padded)
__device__ double g_t[N_NODES];          // row accumulators for norm
__device__ float  g_loss[1];
__device__ float  g_masksum[1];

// ---------------- helpers ----------------
__device__ __forceinline__ float wredsum(float v) {
    #pragma unroll
    for (int o = 16; o > 0; o >>= 1) v += __shfl_xor_sync(0xffffffffu, v, o);
    return v;
}
__device__ __forceinline__ float sigmoidf_(float x) { return 1.0f / (1.0f + expf(-x)); }
__device__ __forceinline__ uint32_t smem_to_u32(const void* smem_ptr) {
    uint32_t addr;
    asm("{ .reg .u64 tmp; cvta.to.shared.u64 tmp, %1; cvt.u32.u64 %0, tmp; }"
        : "=r"(addr) : "l"(smem_ptr));
    return addr;
}

#define LDMATRIX_X4(r0, r1, r2, r3, addr) \
    asm volatile("ldmatrix.sync.aligned.m8n8.x4.shared.b16 {%0,%1,%2,%3}, [%4];" \
        : "=r"(r0), "=r"(r1), "=r"(r2), "=r"(r3) : "r"(addr))
#define LDMATRIX_X2(r0, r1, addr) \
    asm volatile("ldmatrix.sync.aligned.m8n8.x2.shared.b16 {%0,%1}, [%2];" \
        : "=r"(r0), "=r"(r1) : "r"(addr))
#define MMA16816(d, a, b) \
    asm volatile("mma.sync.aligned.m16n8k16.row.col.f32.bf16.bf16.f32 " \
        "{%0,%1,%2,%3}, {%4,%5,%6,%7}, {%8,%9}, {%0,%1,%2,%3};" \
        : "+f"((d)[0]), "+f"((d)[1]), "+f"((d)[2]), "+f"((d)[3]) \
        : "r"((a)[0]), "r"((a)[1]), "r"((a)[2]), "r"((a)[3]), "r"((b)[0]), "r"((b)[1]))

// ---------------- k_init ----------------
__global__ void k_init(const float* __restrict__ logit_p,
                       const float* __restrict__ emb_w,
                       float* __restrict__ pw_out) {
    int f = threadIdx.x;
    if (f < F_DIM) {
        float p = sigmoidf_(logit_p[f]);
        pw_out[f] = 1.0f - p;
        const float EPSf = 2.2204460492503131e-16f;
        float approx = logf(p + EPSf) - logf(1.0f - p + EPSf);
        float keep = 1.0f - sigmoidf_(approx * 10.0f);
        g_kf[f] = keep * sigmoidf_(emb_w[f]);
        if (f == 0) { g_loss[0] = 0.0f; g_masksum[0] = 0.0f; }
    }
}

// ---------------- k_prep: pack W1 ----------------
__global__ void k_prep(const float* __restrict__ W1) {
    int idx = blockIdx.x * 256 + threadIdx.x;
    if (idx >= G_CNT * F_DIM * 32) return;
    int lane = idx & 31;
    int k = (idx >> 5) & 127;
    int g = idx >> 12;
    const float* Wg = W1 + g * F_DIM * H_DIM + k * H_DIM;
    g_W1p[idx] = make_float2(Wg[lane], Wg[lane + 32]);
}

// ---------------- k_ex ----------------
__global__ void k_ex(const float* __restrict__ x, const int* __restrict__ mask) {
    int w = blockIdx.x * 8 + (threadIdx.x >> 5);
    if (w >= NPAD) return;
    int lane = threadIdx.x & 31;
    if (w < N_NODES) {
        float4 kf = *(const float4*)&g_kf[lane * 4];
        float4 xv = *(const float4*)&x[(size_t)w * F_DIM + lane * 4];
        float4 e;
        e.x = __fmul_rn(xv.x, kf.x); e.y = __fmul_rn(xv.y, kf.y);
        e.z = __fmul_rn(xv.z, kf.z); e.w = __fmul_rn(xv.w, kf.w);
        *(float4*)&g_ex[(size_t)w * F_DIM + lane * 4] = e;
        if (lane == 0 && mask[w] > 0) atomicAdd(&g_masksum[0], 1.0f);
    } else {
        *(float4*)&g_ex[(size_t)w * F_DIM + lane * 4] = make_float4(0.f, 0.f, 0.f, 0.f);
    }
    if (lane == 1) { g_cnt[0][w] = 0; g_cnt[1][w] = 0; }
}

// ---------------- k_colinv: SACRED — matched reference emitter order; do not touch ----------------
__global__ void k_colinv(const float* __restrict__ x) {
    int w = blockIdx.x * 8 + (threadIdx.x >> 5);
    if (w >= NPAD) return;
    int lane = threadIdx.x & 31;
    if (w < N_NODES) {
        const float* xr = x + (size_t)w * F_DIM;
        float2 xa = *(const float2*)&xr[2 * lane];
        float2 xb = *(const float2*)&xr[2 * lane + 64];
        float2 ka = *(const float2*)&g_kf[2 * lane];
        float2 kb = *(const float2*)&g_kf[2 * lane + 64];
        float i0 = __fadd_rn(__fmul_rn(xa.x, ka.x), __fmul_rn(xa.y, ka.y));
        float i1 = __fadd_rn(__fmul_rn(xb.x, kb.x), __fmul_rn(xb.y, kb.y));
        float s = __fadd_rn(i0, i1);
        s = wredsum(s);
        if (lane == 0) g_colinv[w] = __fdiv_rn(1.0f, __fadd_rn(s, 1e-6f));
    } else if (lane == 0) {
        g_colinv[w] = 0.0f;
    }
}

// ---------------- k_split: fp32 -> 3-way bf16 split of ex ----------------
__global__ void k_split() {
    size_t i = (size_t)blockIdx.x * 256 + threadIdx.x;
    if (i >= (size_t)NPAD * F_DIM) return;
    float e = g_ex[i];
    __nv_bfloat16 h = __float2bfloat16(e);
    float r = e - __bfloat162float(h);
    __nv_bfloat16 m = __float2bfloat16(r);
    float r2 = r - __bfloat162float(m);
    g_exs[0][i] = h;
    g_exs[1][i] = m;
    g_exs[2][i] = __float2bfloat16(r2);
}

// ---------------- CSR build ----------------
__global__ void k_csr_hist(const int* __restrict__ e0, const int* __restrict__ e1) {
    int idx = blockIdx.x * 256 + threadIdx.x;
    if (idx >= E_EDGES) return;
    const int* ei = blockIdx.y ? e1 : e0;
    atomicAdd(&g_cnt[blockIdx.y][ei[E_EDGES + idx]], 1);
}

__global__ void k_csr_scan() {
    __shared__ int part[1024];
    int t = threadIdx.x;
    for (int list = 0; list < 2; list++) {
        const int chunk = 10;
        int base = t * chunk;
        int sum = 0;
        #pragma unroll
        for (int i = 0; i < chunk; i++) {
            int idx = base + i;
            if (idx < N_NODES) sum += g_cnt[list][idx];
        }
        part[t] = sum;
        __syncthreads();
        for (int off = 1; off < 1024; off <<= 1) {
            int u = (t >= off) ? part[t - off] : 0;
            __syncthreads();
            part[t] += u;
            __syncthreads();
        }
        int run = part[t] - sum;
        for (int i = 0; i < chunk; i++) {
            int idx = base + i;
            if (idx < N_NODES) {
                g_off[list][idx] = run;
                g_cur[list][idx] = run;
                run += g_cnt[list][idx];
            }
        }
        __syncthreads();
    }
}

__global__ void k_csr_scatter(const int* __restrict__ e0, const int* __restrict__ e1) {
    int idx = blockIdx.x * 256 + threadIdx.x;
    if (idx >= E_EDGES) return;
    int list = blockIdx.y;
    const int* ei = list ? e1 : e0;
    int s = ei[idx], d = ei[E_EDGES + idx];
    int pos = atomicAdd(&g_cur[list][d], 1);
    g_csr[list][pos] = s;
}

// ---------------- k_h1_all ----------------
__global__ __launch_bounds__(256) void k_h1_all(const float* __restrict__ x,
                                                const float* __restrict__ as1,
                                                const float* __restrict__ ad1) {
    int warp = blockIdx.x * 8 + (threadIdx.x >> 5);
    int lane = threadIdx.x & 31;
    if (warp >= 2500) return;
    int n0 = warp * 4;

    unsigned long long acc[4][4];
    #pragma unroll
    for (int g = 0; g < 4; g++)
        #pragma unroll
        for (int nd = 0; nd < 4; nd++) acc[g][nd] = 0ull;

    const float* xr = x + (size_t)n0 * F_DIM;
    for (int k = 0; k < F_DIM; k++) {
        unsigned long long xd[4];
        #pragma unroll
        for (int nd = 0; nd < 4; nd++) {
            unsigned xu = __float_as_uint(__ldg(xr + nd * F_DIM + k));
            asm("mov.b64 %0, {%1, %1};" : "=l"(xd[nd]) : "r"(xu));
        }
        #pragma unroll
        for (int g = 0; g < 4; g++) {
            float2 wv = g_W1p[(g * F_DIM + k) * 32 + lane];
            unsigned long long wd = *reinterpret_cast<unsigned long long*>(&wv);
            #pragma unroll
            for (int nd = 0; nd < 4; nd++)
                asm("fma.rn.f32x2 %0, %1, %2, %0;"
                    : "+l"(acc[g][nd]) : "l"(xd[nd]), "l"(wd));
        }
    }
    #pragma unroll
    for (int g = 0; g < 4; g++) {
        float asl = as1[g * 64 + lane], ash = as1[g * 64 + lane + 32];
        float adl = ad1[g * 64 + lane], adh = ad1[g * 64 + lane + 32];
        #pragma unroll
        for (int nd = 0; nd < 4; nd++) {
            unsigned long long v = acc[g][nd];
            float lo = __uint_as_float((unsigned)(v & 0xffffffffull));
            float hi = __uint_as_float((unsigned)(v >> 32));
            g_h1p[((size_t)g * N_NODES + n0 + nd) * 32 + lane] = make_float2(lo, hi);
            float ap = wredsum(lo * asl + hi * ash);
            float rp = wredsum(lo * adl + hi * adh);
            if (lane == 0) {
                g_al4[g * N_NODES + n0 + nd] = ap;
                g_ar4[g * N_NODES + n0 + nd] = rp;
            }
        }
    }
}

// ---------------- k_gat1_all ----------------
__global__ void k_gat1_all(const float* __restrict__ b1, const float* __restrict__ gm,
                           const float* __restrict__ bt, const float* __restrict__ W2,
                           const float* __restrict__ as2, const float* __restrict__ ad2) {
    int g = blockIdx.y, list = g & 1;
    int d = blockIdx.x * 8 + (threadIdx.x >> 5);
    if (d >= N_NODES) return;
    int lane = threadIdx.x & 31;

    const float* al = g_al4 + g * N_NODES;
    float ard = g_ar4[g * N_NODES + d];
    const float2* h1p = g_h1p + (size_t)g * N_NODES * 32;

    float a0 = al[d] + ard; a0 = (a0 >= 0.f) ? a0 : 0.2f * a0;
    float ee = expf(a0);
    float2 hd = h1p[d * 32 + lane];
    float accx = ee * hd.x, accy = ee * hd.y, s = ee;

    int k1 = g_off[list][d] + g_cnt[list][d];
    for (int k = g_off[list][d]; k < k1; k++) {
        int src = g_csr[list][k];
        float a = al[src] + ard; a = (a >= 0.f) ? a : 0.2f * a;
        float e = expf(a);
        float2 h = h1p[src * 32 + lane];
        s += e;
        accx = fmaf(e, h.x, accx);
        accy = fmaf(e, h.y, accy);
    }
    float inv = 1.0f / (s + 1e-16f);
    float h0  = accx * inv + b1[g * 64 + lane];
    float h1v = accy * inv + b1[g * 64 + lane + 32];
    const float BNS = 0.9999950000374997f;
    h0  = h0  * gm[g * 64 + lane]      * BNS + bt[g * 64 + lane];
    h1v = h1v * gm[g * 64 + lane + 32] * BNS + bt[g * 64 + lane + 32];
    h0  = (h0  >= 0.f) ? h0  : 0.01f * h0;
    h1v = (h1v >= 0.f) ? h1v : 0.01f * h1v;
    const float* W2g = W2 + g * H_DIM * C_DIM;
    float p0 = wredsum(h0 * W2g[lane * 2]     + h1v * W2g[(lane + 32) * 2]);
    float p1 = wredsum(h0 * W2g[lane * 2 + 1] + h1v * W2g[(lane + 32) * 2 + 1]);
    if (lane == 0) {
        g_h2a[g * N_NODES + d] = make_float2(p0, p1);
        g_al2a[g * N_NODES + d] = p0 * as2[g * 2] + p1 * as2[g * 2 + 1];
        g_ar2a[g * N_NODES + d] = p0 * ad2[g * 2] + p1 * ad2[g * 2 + 1];
    }
}

// ---------------- k_gat2_all ----------------
__global__ void k_gat2_all(const float* __restrict__ b2, const int* __restrict__ y,
                           const int* __restrict__ mask) {
    int g = blockIdx.y, list = g & 1;
    int d = blockIdx.x * 8 + (threadIdx.x >> 5);
    if (d >= N_NODES) return;
    int lane = threadIdx.x & 31;

    const float* al2 = g_al2a + g * N_NODES;
    float ar2d = g_ar2a[g * N_NODES + d];
    const float2* h2 = g_h2a + g * N_NODES;

    float s = 0.f, o0 = 0.f, o1 = 0.f;
    int k0 = g_off[list][d], k1 = k0 + g_cnt[list][d];
    for (int k = k0 + lane; k < k1; k += 32) {
        int src = g_csr[list][k];
        float a = al2[src] + ar2d; a = (a >= 0.f) ? a : 0.2f * a;
        float e = expf(a);
        float2 h = h2[src];
        s += e;
        o0 = fmaf(e, h.x, o0);
        o1 = fmaf(e, h.y, o1);
    }
    s = wredsum(s); o0 = wredsum(o0); o1 = wredsum(o1);
    if (lane == 0) {
        float a = al2[d] + ar2d; a = (a >= 0.f) ? a : 0.2f * a;
        float es = expf(a);
        float2 hd = h2[d];
        s += es; o0 += es * hd.x; o1 += es * hd.y;
        float inv = 1.0f / (s + 1e-16f);
        float v0 = o0 * inv + b2[g * 2];
        float v1 = o1 * inv + b2[g * 2 + 1];
        float mx = fmaxf(v0, v1);
        float lse = mx + logf(expf(v0 - mx) + expf(v1 - mx));
        float lp0 = v0 - lse, lp1 = v1 - lse;
        g_oacc[g][d] = expf(lp1);
        if (mask[d] > 0) atomicAdd(&g_loss[0], (y[d] == 0) ? lp0 : lp1);
    }
}

// ---------------- k_nodep ----------------
__global__ void k_nodep(float* __restrict__ dout) {
    int i = blockIdx.x * blockDim.x + threadIdx.x;
    if (i < NPAD) {
        if (i < N_NODES) {
            float p = (((g_oacc[0][i] + g_oacc[1][i]) + g_oacc[2][i]) + g_oacc[3][i]) * 0.25f;
            dout[i] = p;
            g_w2[i] = 2.0f * p - 1.0f;
            g_t[i] = 0.0;
        } else {
            g_w2[i] = 0.0f;
        }
    }
    if (i == 0) dout[N_NODES] = -g_loss[0] / (g_masksum[0] * (float)G_CNT);
}

// ---------------- k_graph_mma: mma.sync bf16x3 GEMM, triangular, fused t ----------------
// smem: 6 bf16 tiles 128 rows x 272B (padded, ldmatrix conflict-free), then reuse
// as float Cst[128][133] for the epilogue.
#define TSTRIDE   272
#define TILE_B    (128 * TSTRIDE)          // 34816
#define SMEM_MMA  (1024 + 6 * TILE_B)      // 209920

__global__ __launch_bounds__(256, 1) void k_graph_mma(float* __restrict__ out) {
    extern __shared__ char smem[];
    int bib = blockIdx.y, bjb = blockIdx.x;
    if (bjb < bib) return;
    int bi = bib * 128, bj = bjb * 128;
    int tid = threadIdx.x;
    int wid = tid >> 5, lane = tid & 31;
    uint32_t tbase = smem_to_u32(smem) + 1024;

    // Fill 6 tiles: q 0..2 = A splits (rows bi..), q 3..5 = B splits (rows bj..)
    #pragma unroll 1
    for (int q = 0; q < 6; q++) {
        int s = (q < 3) ? q : q - 3;
        int base_row = (q < 3) ? bi : bj;
        char* dst = smem + 1024 + q * TILE_B;
        const __nv_bfloat16* src = g_exs[s] + (size_t)base_row * F_DIM;
        #pragma unroll
        for (int it = 0; it < 8; it++) {
            int t = it * 256 + tid;            // 0..2047
            int row = t >> 4, ch = t & 15;
            uint4 v = *(const uint4*)&src[(size_t)row * F_DIM + ch * 8];
            *(uint4*)(dst + row * TSTRIDE + ch * 16) = v;
        }
    }
    __syncthreads();

    // Warp layout: 2 (M) x 4 (N); warp tile 64x32
    int mw = wid & 1, nw = wid >> 1;
    float acc[4][4][4];
    #pragma unroll
    for (int mf = 0; mf < 4; mf++)
        #pragma unroll
        for (int nf = 0; nf < 4; nf++)
            #pragma unroll
            for (int r = 0; r < 4; r++) acc[mf][nf][r] = 0.f;

    int rowA = mw * 64 + (lane & 15);
    int kselA = ((lane >> 4) << 3);           // 0 or 8
    int rowB = nw * 32 + (lane & 7);
    int kselB = (lane & 8);                   // 0 or 8

    #pragma unroll 1
    for (int ks = 0; ks < 8; ks++) {
        int kb = ks * 16;
        #pragma unroll 1
        for (int sA = 0; sA < 3; sA++) {
            uint32_t a[4][4];
            uint32_t abase = tbase + sA * TILE_B + (kb + kselA) * 2;
            #pragma unroll
            for (int mf = 0; mf < 4; mf++) {
                uint32_t ad = abase + (rowA + mf * 16) * TSTRIDE;
                LDMATRIX_X4(a[mf][0], a[mf][1], a[mf][2], a[mf][3], ad);
            }
            int nB = (sA == 0) ? 3 : ((sA == 1) ? 2 : 1);
            #pragma unroll 1
            for (int sB = 0; sB < nB; sB++) {
                uint32_t b[4][2];
                uint32_t bbase = tbase + (3 + sB) * TILE_B + (kb + kselB) * 2;
                #pragma unroll
                for (int nf = 0; nf < 4; nf++) {
                    uint32_t bd = bbase + (rowB + nf * 8) * TSTRIDE;
                    LDMATRIX_X2(b[nf][0], b[nf][1], bd);
                }
                #pragma unroll
                for (int mf = 0; mf < 4; mf++)
                    #pragma unroll
                    for (int nf = 0; nf < 4; nf++)
                        MMA16816(acc[mf][nf], a[mf], b[nf]);
            }
        }
    }
    __syncthreads();   // all warps done reading tiles; reuse smem as Cst

    float* Cst = (float*)(smem + 1024);
    {
        int qr = lane >> 2;            // 0..7
        int qc = (lane & 3) * 2;       // 0,2,4,6
        #pragma unroll
        for (int mf = 0; mf < 4; mf++) {
            int m = mw * 64 + mf * 16 + qr;
            #pragma unroll
            for (int nf = 0; nf < 4; nf++) {
                int n = nw * 32 + nf * 8 + qc;
                Cst[m * 133 + n]           = acc[mf][nf][0];
                Cst[m * 133 + n + 1]       = acc[mf][nf][1];
                Cst[(m + 8) * 133 + n]     = acc[mf][nf][2];
                Cst[(m + 8) * 133 + n + 1] = acc[mf][nf][3];
            }
        }
    }
    __syncthreads();

    // Direct emission: out[bi+m][bj+n] = C[m][n]*colinv[bj+n]; t[bi+m] += val*w2
    {
        float cjv[4], wjv[4];
        #pragma unroll
        for (int nb = 0; nb < 4; nb++) {
            int cj = bj + nb * 32 + lane;
            cjv[nb] = g_colinv[cj];
            wjv[nb] = g_w2[cj];
        }
        #pragma unroll 1
        for (int k = 0; k < 16; k++) {
            int m = wid * 16 + k;
            int r = bi + m;
            if (r >= N_NODES) continue;
            float acc2 = 0.f;
            size_t rowb = (size_t)r * N_NODES;
            #pragma unroll
            for (int nb = 0; nb < 4; nb++) {
                int cj = bj + nb * 32 + lane;
                float val = __fmul_rn(Cst[m * 133 + nb * 32 + lane], cjv[nb]);
                if (cj < N_NODES) out[rowb + cj] = val;
                acc2 = fmaf(val, wjv[nb], acc2);
            }
            acc2 = wredsum(acc2);
            if (lane == 0) atomicAdd(&g_t[r], (double)acc2);
        }
    }

    // Transposed emission (off-diagonal): out[bj+n][bi+m] = C[m][n]*colinv[bi+m]
    if (bib != bjb) {
        float civ[4], wv[4];
        #pragma unroll
        for (int mb = 0; mb < 4; mb++) {
            int ri = bi + mb * 32 + lane;
            civ[mb] = g_colinv[ri];
            wv[mb] = g_w2[ri];
        }
        #pragma unroll 1
        for (int k = 0; k < 16; k++) {
            int n = wid * 16 + k;
            int cg = bj + n;
            if (cg >= N_NODES) continue;
            float acc2 = 0.f;
            size_t rowb = (size_t)cg * N_NODES;
            #pragma unroll
            for (int mb = 0; mb < 4; mb++) {
                int ri = bi + mb * 32 + lane;
                float val = __fmul_rn(Cst[(mb * 32 + lane) * 133 + n], civ[mb]);
                if (ri < N_NODES) out[rowb + ri] = val;
                acc2 = fmaf(val, wv[mb], acc2);
            }
            acc2 = wredsum(acc2);
            if (lane == 0) atomicAdd(&g_t[cg], (double)acc2);
        }
    }
}

// ---------------- k_normf ----------------
__global__ void k_normf(float* __restrict__ outp) {
    int i = blockIdx.x * blockDim.x + threadIdx.x;
    if (i >= N_NODES) return;
    float t = (float)g_t[i];
    outp[i] = 1.0f / (1.0f + expf(-t));
}

// ---------------- launch ----------------
extern "C" void kernel_launch(void* const* d_in, const int* in_sizes, int n_in,
                              void* d_out, int out_size) {
    const float* x      = (const float*)d_in[0];
    const int*   y      = (const int*)d_in[1];
    const int*   mask   = (const int*)d_in[2];
    const int*   e_ppi  = (const int*)d_in[3];
    const int*   e_hom  = (const int*)d_in[4];
    const float* W1     = (const float*)d_in[5];
    const float* as1    = (const float*)d_in[6];
    const float* ad1    = (const float*)d_in[7];
    const float* b1     = (const float*)d_in[8];
    const float* gamma_ = (const float*)d_in[9];
    const float* beta_  = (const float*)d_in[10];
    const float* W2     = (const float*)d_in[11];
    const float* as2    = (const float*)d_in[12];
    const float* ad2    = (const float*)d_in[13];
    const float* b2     = (const float*)d_in[14];
    const float* emb_w  = (const float*)d_in[15];
    const float* logitp = (const float*)d_in[16];
    float* out = (float*)d_out;

    const size_t OFF_NORM  = (size_t)N_NODES + 1;
    const size_t OFF_GRAPH = (size_t)2 * N_NODES + 1;
    const size_t OFF_PW    = OFF_GRAPH + (size_t)N_NODES * N_NODES;

    cudaFuncSetAttribute(k_graph_mma, cudaFuncAttributeMaxDynamicSharedMemorySize, SMEM_MMA);

    k_init<<<1, 128>>>(logitp, emb_w, out + OFF_PW);
    k_prep<<<(G_CNT * F_DIM * 32 + 255) / 256, 256>>>(W1);
    k_ex<<<NPAD / 8, 256>>>(x, mask);
    k_colinv<<<NPAD / 8, 256>>>(x);
    k_split<<<(NPAD * F_DIM + 255) / 256, 256>>>();

    dim3 eg((E_EDGES + 255) / 256, 2);
    k_csr_hist<<<eg, 256>>>(e_ppi, e_hom);
    k_csr_scan<<<1, 1024>>>();
    k_csr_scatter<<<eg, 256>>>(e_ppi, e_hom);

    k_h1_all<<<313, 256>>>(x, as1, ad1);

    dim3 gg1(1250, G_CNT);
    k_gat1_all<<<gg1, 256>>>(b1, gamma_, beta_, W2, as2, ad2);
    k_gat2_all<<<gg1, 256>>>(b2, y, mask);

    k_nodep<<<(NPAD + 255) / 256, 256>>>(out);
    dim3 ggr(79, 79);
    k_graph_mma<<<ggr, 256, SMEM_MMA>>>(out + OFF_GRAPH);
    k_normf<<<(N_NODES + 255) / 256, 256>>>(out + OFF_NORM);
}

// round 13
// speedup vs baseline: 2.1369x; 1.0821x over previous
#include <cuda_runtime.h>
#include <cuda_bf16.h>
#include <cstdint>
#include <math.h>

#define N_NODES 10000
#define F_DIM   128
#define H_DIM   64
#define C_DIM   2
#define G_CNT   4
#define E_EDGES 320000
#define NPAD    10112                  // 79 * 128

// ---------------- scratch (device globals; no dynamic alloc) ----------------
__device__ float  g_kf[F_DIM];
__device__ float  g_ex[(size_t)NPAD * F_DIM];
__device__ __align__(16) __nv_bfloat16 g_exs[3][(size_t)NPAD * F_DIM];  // hi/mid/lo splits
__device__ float  g_colinv[NPAD];
__device__ float2 g_W1p[G_CNT * F_DIM * 32];               // packed (c, c+32) pairs
__device__ float2 g_h1p[(size_t)G_CNT * N_NODES * 32];     // packed h1
__device__ float  g_al4[G_CNT * N_NODES], g_ar4[G_CNT * N_NODES];
__device__ float  g_al2a[G_CNT * N_NODES], g_ar2a[G_CNT * N_NODES];
__device__ float2 g_h2a[G_CNT * N_NODES];
__device__ float  g_oacc[G_CNT][N_NODES];
__device__ int    g_cnt[2][NPAD];
__device__ int    g_off[2][NPAD];
__device__ int    g_cur[2][NPAD];
__device__ int    g_csr[2][E_EDGES];
__device__ float  g_w2[NPAD];            // 2p-1 (zero padded)
__device__ double g_t[N_NODES];          // row accumulators for norm
__device__ float  g_loss[1];
__device__ float  g_masksum[1];

// ---------------- helpers ----------------
__device__ __forceinline__ float wredsum(float v) {
    #pragma unroll
    for (int o = 16; o > 0; o >>= 1) v += __shfl_xor_sync(0xffffffffu, v, o);
    return v;
}
__device__ __forceinline__ float sigmoidf_(float x) { return 1.0f / (1.0f + expf(-x)); }
__device__ __forceinline__ uint32_t smem_to_u32(const void* smem_ptr) {
    uint32_t addr;
    asm("{ .reg .u64 tmp; cvta.to.shared.u64 tmp, %1; cvt.u32.u64 %0, tmp; }"
        : "=r"(addr) : "l"(smem_ptr));
    return addr;
}

#define LDMATRIX_X4(r0, r1, r2, r3, addr) \
    asm volatile("ldmatrix.sync.aligned.m8n8.x4.shared.b16 {%0,%1,%2,%3}, [%4];" \
        : "=r"(r0), "=r"(r1), "=r"(r2), "=r"(r3) : "r"(addr))
#define LDMATRIX_X2(r0, r1, addr) \
    asm volatile("ldmatrix.sync.aligned.m8n8.x2.shared.b16 {%0,%1}, [%2];" \
        : "=r"(r0), "=r"(r1) : "r"(addr))
#define MMA16816(d, a, b) \
    asm volatile("mma.sync.aligned.m16n8k16.row.col.f32.bf16.bf16.f32 " \
        "{%0,%1,%2,%3}, {%4,%5,%6,%7}, {%8,%9}, {%0,%1,%2,%3};" \
        : "+f"((d)[0]), "+f"((d)[1]), "+f"((d)[2]), "+f"((d)[3]) \
        : "r"((a)[0]), "r"((a)[1]), "r"((a)[2]), "r"((a)[3]), "r"((b)[0]), "r"((b)[1]))

// ---------------- k_init ----------------
__global__ void k_init(const float* __restrict__ logit_p,
                       const float* __restrict__ emb_w,
                       float* __restrict__ pw_out) {
    int f = threadIdx.x;
    if (f < F_DIM) {
        float p = sigmoidf_(logit_p[f]);
        pw_out[f] = 1.0f - p;
        const float EPSf = 2.2204460492503131e-16f;
        float approx = logf(p + EPSf) - logf(1.0f - p + EPSf);
        float keep = 1.0f - sigmoidf_(approx * 10.0f);
        g_kf[f] = keep * sigmoidf_(emb_w[f]);
        if (f == 0) { g_loss[0] = 0.0f; g_masksum[0] = 0.0f; }
    }
}

// ---------------- k_prep: pack W1 ----------------
__global__ void k_prep(const float* __restrict__ W1) {
    int idx = blockIdx.x * 256 + threadIdx.x;
    if (idx >= G_CNT * F_DIM * 32) return;
    int lane = idx & 31;
    int k = (idx >> 5) & 127;
    int g = idx >> 12;
    const float* Wg = W1 + g * F_DIM * H_DIM + k * H_DIM;
    g_W1p[idx] = make_float2(Wg[lane], Wg[lane + 32]);
}

// ---------------- k_ex: ex = x*kf (exact), bf16x3 split fused, masksum ----------------
__global__ void k_ex(const float* __restrict__ x, const int* __restrict__ mask) {
    int w = blockIdx.x * 8 + (threadIdx.x >> 5);
    if (w >= NPAD) return;
    int lane = threadIdx.x & 31;
    size_t base = (size_t)w * F_DIM + lane * 4;
    float4 e = make_float4(0.f, 0.f, 0.f, 0.f);
    if (w < N_NODES) {
        float4 kf = *(const float4*)&g_kf[lane * 4];
        float4 xv = *(const float4*)&x[base];
        e.x = __fmul_rn(xv.x, kf.x); e.y = __fmul_rn(xv.y, kf.y);
        e.z = __fmul_rn(xv.z, kf.z); e.w = __fmul_rn(xv.w, kf.w);
        if (lane == 0 && mask[w] > 0) atomicAdd(&g_masksum[0], 1.0f);
    }
    *(float4*)&g_ex[base] = e;
    // 3-way bf16 split (fused)
    const float* ep = (const float*)&e;
    __nv_bfloat16 hs[4], ms[4], ls[4];
    #pragma unroll
    for (int q = 0; q < 4; q++) {
        float v = ep[q];
        __nv_bfloat16 h = __float2bfloat16(v);
        float r = v - __bfloat162float(h);
        __nv_bfloat16 m = __float2bfloat16(r);
        float r2 = r - __bfloat162float(m);
        hs[q] = h; ms[q] = m; ls[q] = __float2bfloat16(r2);
    }
    *(uint2*)&g_exs[0][base] = *(uint2*)hs;
    *(uint2*)&g_exs[1][base] = *(uint2*)ms;
    *(uint2*)&g_exs[2][base] = *(uint2*)ls;
    if (lane == 1) { g_cnt[0][w] = 0; g_cnt[1][w] = 0; }
}

// ---------------- k_colinv: SACRED — matched reference emitter order; do not touch ----------------
__global__ void k_colinv(const float* __restrict__ x) {
    int w = blockIdx.x * 8 + (threadIdx.x >> 5);
    if (w >= NPAD) return;
    int lane = threadIdx.x & 31;
    if (w < N_NODES) {
        const float* xr = x + (size_t)w * F_DIM;
        float2 xa = *(const float2*)&xr[2 * lane];
        float2 xb = *(const float2*)&xr[2 * lane + 64];
        float2 ka = *(const float2*)&g_kf[2 * lane];
        float2 kb = *(const float2*)&g_kf[2 * lane + 64];
        float i0 = __fadd_rn(__fmul_rn(xa.x, ka.x), __fmul_rn(xa.y, ka.y));
        float i1 = __fadd_rn(__fmul_rn(xb.x, kb.x), __fmul_rn(xb.y, kb.y));
        float s = __fadd_rn(i0, i1);
        s = wredsum(s);
        if (lane == 0) g_colinv[w] = __fdiv_rn(1.0f, __fadd_rn(s, 1e-6f));
    } else if (lane == 0) {
        g_colinv[w] = 0.0f;
    }
}

// ---------------- CSR build ----------------
__global__ void k_csr_hist(const int* __restrict__ e0, const int* __restrict__ e1) {
    int idx = blockIdx.x * 256 + threadIdx.x;
    if (idx >= E_EDGES) return;
    const int* ei = blockIdx.y ? e1 : e0;
    atomicAdd(&g_cnt[blockIdx.y][ei[E_EDGES + idx]], 1);
}

__global__ void k_csr_scan() {
    __shared__ int part[1024];
    int t = threadIdx.x;
    for (int list = 0; list < 2; list++) {
        const int chunk = 10;
        int base = t * chunk;
        int sum = 0;
        #pragma unroll
        for (int i = 0; i < chunk; i++) {
            int idx = base + i;
            if (idx < N_NODES) sum += g_cnt[list][idx];
        }
        part[t] = sum;
        __syncthreads();
        for (int off = 1; off < 1024; off <<= 1) {
            int u = (t >= off) ? part[t - off] : 0;
            __syncthreads();
            part[t] += u;
            __syncthreads();
        }
        int run = part[t] - sum;
        for (int i = 0; i < chunk; i++) {
            int idx = base + i;
            if (idx < N_NODES) {
                g_off[list][idx] = run;
                g_cur[list][idx] = run;
                run += g_cnt[list][idx];
            }
        }
        __syncthreads();
    }
}

__global__ void k_csr_scatter(const int* __restrict__ e0, const int* __restrict__ e1) {
    int idx = blockIdx.x * 256 + threadIdx.x;
    if (idx >= E_EDGES) return;
    int list = blockIdx.y;
    const int* ei = list ? e1 : e0;
    int s = ei[idx], d = ei[E_EDGES + idx];
    int pos = atomicAdd(&g_cur[list][d], 1);
    g_csr[list][pos] = s;
}

// ---------------- k_h1_all ----------------
__global__ __launch_bounds__(256) void k_h1_all(const float* __restrict__ x,
                                                const float* __restrict__ as1,
                                                const float* __restrict__ ad1) {
    int warp = blockIdx.x * 8 + (threadIdx.x >> 5);
    int lane = threadIdx.x & 31;
    if (warp >= 2500) return;
    int n0 = warp * 4;

    unsigned long long acc[4][4];
    #pragma unroll
    for (int g = 0; g < 4; g++)
        #pragma unroll
        for (int nd = 0; nd < 4; nd++) acc[g][nd] = 0ull;

    const float* xr = x + (size_t)n0 * F_DIM;
    for (int k = 0; k < F_DIM; k++) {
        unsigned long long xd[4];
        #pragma unroll
        for (int nd = 0; nd < 4; nd++) {
            unsigned xu = __float_as_uint(__ldg(xr + nd * F_DIM + k));
            asm("mov.b64 %0, {%1, %1};" : "=l"(xd[nd]) : "r"(xu));
        }
        #pragma unroll
        for (int g = 0; g < 4; g++) {
            float2 wv = g_W1p[(g * F_DIM + k) * 32 + lane];
            unsigned long long wd = *reinterpret_cast<unsigned long long*>(&wv);
            #pragma unroll
            for (int nd = 0; nd < 4; nd++)
                asm("fma.rn.f32x2 %0, %1, %2, %0;"
                    : "+l"(acc[g][nd]) : "l"(xd[nd]), "l"(wd));
        }
    }
    #pragma unroll
    for (int g = 0; g < 4; g++) {
        float asl = as1[g * 64 + lane], ash = as1[g * 64 + lane + 32];
        float adl = ad1[g * 64 + lane], adh = ad1[g * 64 + lane + 32];
        #pragma unroll
        for (int nd = 0; nd < 4; nd++) {
            unsigned long long v = acc[g][nd];
            float lo = __uint_as_float((unsigned)(v & 0xffffffffull));
            float hi = __uint_as_float((unsigned)(v >> 32));
            g_h1p[((size_t)g * N_NODES + n0 + nd) * 32 + lane] = make_float2(lo, hi);
            float ap = wredsum(lo * asl + hi * ash);
            float rp = wredsum(lo * adl + hi * adh);
            if (lane == 0) {
                g_al4[g * N_NODES + n0 + nd] = ap;
                g_ar4[g * N_NODES + n0 + nd] = rp;
            }
        }
    }
}

// ---------------- k_gat1_all ----------------
__global__ void k_gat1_all(const float* __restrict__ b1, const float* __restrict__ gm,
                           const float* __restrict__ bt, const float* __restrict__ W2,
                           const float* __restrict__ as2, const float* __restrict__ ad2) {
    int g = blockIdx.y, list = g & 1;
    int d = blockIdx.x * 8 + (threadIdx.x >> 5);
    if (d >= N_NODES) return;
    int lane = threadIdx.x & 31;

    const float* al = g_al4 + g * N_NODES;
    float ard = g_ar4[g * N_NODES + d];
    const float2* h1p = g_h1p + (size_t)g * N_NODES * 32;

    float a0 = al[d] + ard; a0 = (a0 >= 0.f) ? a0 : 0.2f * a0;
    float ee = expf(a0);
    float2 hd = h1p[d * 32 + lane];
    float accx = ee * hd.x, accy = ee * hd.y, s = ee;

    int k1 = g_off[list][d] + g_cnt[list][d];
    for (int k = g_off[list][d]; k < k1; k++) {
        int src = g_csr[list][k];
        float a = al[src] + ard; a = (a >= 0.f) ? a : 0.2f * a;
        float e = expf(a);
        float2 h = h1p[src * 32 + lane];
        s += e;
        accx = fmaf(e, h.x, accx);
        accy = fmaf(e, h.y, accy);
    }
    float inv = 1.0f / (s + 1e-16f);
    float h0  = accx * inv + b1[g * 64 + lane];
    float h1v = accy * inv + b1[g * 64 + lane + 32];
    const float BNS = 0.9999950000374997f;
    h0  = h0  * gm[g * 64 + lane]      * BNS + bt[g * 64 + lane];
    h1v = h1v * gm[g * 64 + lane + 32] * BNS + bt[g * 64 + lane + 32];
    h0  = (h0  >= 0.f) ? h0  : 0.01f * h0;
    h1v = (h1v >= 0.f) ? h1v : 0.01f * h1v;
    const float* W2g = W2 + g * H_DIM * C_DIM;
    float p0 = wredsum(h0 * W2g[lane * 2]     + h1v * W2g[(lane + 32) * 2]);
    float p1 = wredsum(h0 * W2g[lane * 2 + 1] + h1v * W2g[(lane + 32) * 2 + 1]);
    if (lane == 0) {
        g_h2a[g * N_NODES + d] = make_float2(p0, p1);
        g_al2a[g * N_NODES + d] = p0 * as2[g * 2] + p1 * as2[g * 2 + 1];
        g_ar2a[g * N_NODES + d] = p0 * ad2[g * 2] + p1 * ad2[g * 2 + 1];
    }
}

// ---------------- k_gat2_all ----------------
__global__ void k_gat2_all(const float* __restrict__ b2, const int* __restrict__ y,
                           const int* __restrict__ mask) {
    int g = blockIdx.y, list = g & 1;
    int d = blockIdx.x * 8 + (threadIdx.x >> 5);
    if (d >= N_NODES) return;
    int lane = threadIdx.x & 31;

    const float* al2 = g_al2a + g * N_NODES;
    float ar2d = g_ar2a[g * N_NODES + d];
    const float2* h2 = g_h2a + g * N_NODES;

    float s = 0.f, o0 = 0.f, o1 = 0.f;
    int k0 = g_off[list][d], k1 = k0 + g_cnt[list][d];
    for (int k = k0 + lane; k < k1; k += 32) {
        int src = g_csr[list][k];
        float a = al2[src] + ar2d; a = (a >= 0.f) ? a : 0.2f * a;
        float e = expf(a);
        float2 h = h2[src];
        s += e;
        o0 = fmaf(e, h.x, o0);
        o1 = fmaf(e, h.y, o1);
    }
    s = wredsum(s); o0 = wredsum(o0); o1 = wredsum(o1);
    if (lane == 0) {
        float a = al2[d] + ar2d; a = (a >= 0.f) ? a : 0.2f * a;
        float es = expf(a);
        float2 hd = h2[d];
        s += es; o0 += es * hd.x; o1 += es * hd.y;
        float inv = 1.0f / (s + 1e-16f);
        float v0 = o0 * inv + b2[g * 2];
        float v1 = o1 * inv + b2[g * 2 + 1];
        float mx = fmaxf(v0, v1);
        float lse = mx + logf(expf(v0 - mx) + expf(v1 - mx));
        float lp0 = v0 - lse, lp1 = v1 - lse;
        g_oacc[g][d] = expf(lp1);
        if (mask[d] > 0) atomicAdd(&g_loss[0], (y[d] == 0) ? lp0 : lp1);
    }
}

// ---------------- k_nodep ----------------
__global__ void k_nodep(float* __restrict__ dout) {
    int i = blockIdx.x * blockDim.x + threadIdx.x;
    if (i < NPAD) {
        if (i < N_NODES) {
            float p = (((g_oacc[0][i] + g_oacc[1][i]) + g_oacc[2][i]) + g_oacc[3][i]) * 0.25f;
            dout[i] = p;
            g_w2[i] = 2.0f * p - 1.0f;
            g_t[i] = 0.0;
        } else {
            g_w2[i] = 0.0f;
        }
    }
    if (i == 0) dout[N_NODES] = -g_loss[0] / (g_masksum[0] * (float)G_CNT);
}

// ---------------- k_graph_mma: mma.sync bf16x3 GEMM, 512 threads, triangular, fused t ----------------
#define TSTRIDE   272
#define TILE_B    (128 * TSTRIDE)          // 34816
#define SMEM_MMA  (1024 + 6 * TILE_B)      // 209920

__global__ __launch_bounds__(512, 1) void k_graph_mma(float* __restrict__ out) {
    extern __shared__ char smem[];
    int bib = blockIdx.y, bjb = blockIdx.x;
    if (bjb < bib) return;
    int bi = bib * 128, bj = bjb * 128;
    int tid = threadIdx.x;
    int wid = tid >> 5, lane = tid & 31;
    uint32_t tbase = smem_to_u32(smem) + 1024;

    // Fill 6 tiles (512 threads: 4 uint4 per thread per tile)
    #pragma unroll 1
    for (int q = 0; q < 6; q++) {
        int s = (q < 3) ? q : q - 3;
        int base_row = (q < 3) ? bi : bj;
        char* dst = smem + 1024 + q * TILE_B;
        const __nv_bfloat16* src = g_exs[s] + (size_t)base_row * F_DIM;
        #pragma unroll
        for (int it = 0; it < 4; it++) {
            int t = it * 512 + tid;            // 0..2047
            int row = t >> 4, ch = t & 15;
            uint4 v = *(const uint4*)&src[(size_t)row * F_DIM + ch * 8];
            *(uint4*)(dst + row * TSTRIDE + ch * 16) = v;
        }
    }
    __syncthreads();

    // Warp layout: 4 (M) x 4 (N); warp tile 32x32
    int mw = wid & 3, nw = wid >> 2;
    float acc[2][4][4];
    #pragma unroll
    for (int mf = 0; mf < 2; mf++)
        #pragma unroll
        for (int nf = 0; nf < 4; nf++)
            #pragma unroll
            for (int r = 0; r < 4; r++) acc[mf][nf][r] = 0.f;

    int rowA = mw * 32 + (lane & 15);
    int kselA = ((lane >> 4) << 3);           // 0 or 8
    int rowB = nw * 32 + (lane & 7);
    int kselB = (lane & 8);                   // 0 or 8

    #pragma unroll 1
    for (int ks = 0; ks < 8; ks++) {
        int kb = ks * 16;
        #pragma unroll 1
        for (int sA = 0; sA < 3; sA++) {
            uint32_t a[2][4];
            uint32_t abase = tbase + sA * TILE_B + (kb + kselA) * 2;
            #pragma unroll
            for (int mf = 0; mf < 2; mf++) {
                uint32_t ad = abase + (rowA + mf * 16) * TSTRIDE;
                LDMATRIX_X4(a[mf][0], a[mf][1], a[mf][2], a[mf][3], ad);
            }
            int nB = (sA == 0) ? 3 : ((sA == 1) ? 2 : 1);
            #pragma unroll 1
            for (int sB = 0; sB < nB; sB++) {
                uint32_t b[4][2];
                uint32_t bbase = tbase + (3 + sB) * TILE_B + (kb + kselB) * 2;
                #pragma unroll
                for (int nf = 0; nf < 4; nf++) {
                    uint32_t bd = bbase + (rowB + nf * 8) * TSTRIDE;
                    LDMATRIX_X2(b[nf][0], b[nf][1], bd);
                }
                #pragma unroll
                for (int mf = 0; mf < 2; mf++)
                    #pragma unroll
                    for (int nf = 0; nf < 4; nf++)
                        MMA16816(acc[mf][nf], a[mf], b[nf]);
            }
        }
    }
    __syncthreads();   // all warps done reading tiles; reuse smem as Cst

    float* Cst = (float*)(smem + 1024);
    {
        int qr = lane >> 2;            // 0..7
        int qc = (lane & 3) * 2;       // 0,2,4,6
        #pragma unroll
        for (int mf = 0; mf < 2; mf++) {
            int m = mw * 32 + mf * 16 + qr;
            #pragma unroll
            for (int nf = 0; nf < 4; nf++) {
                int n = nw * 32 + nf * 8 + qc;
                Cst[m * 133 + n]           = acc[mf][nf][0];
                Cst[m * 133 + n + 1]       = acc[mf][nf][1];
                Cst[(m + 8) * 133 + n]     = acc[mf][nf][2];
                Cst[(m + 8) * 133 + n + 1] = acc[mf][nf][3];
            }
        }
    }
    __syncthreads();

    // Direct emission: out[bi+m][bj+n] = C[m][n]*colinv[bj+n]; t[bi+m] += val*w2
    {
        float cjv[4], wjv[4];
        #pragma unroll
        for (int nb = 0; nb < 4; nb++) {
            int cj = bj + nb * 32 + lane;
            cjv[nb] = g_colinv[cj];
            wjv[nb] = g_w2[cj];
        }
        #pragma unroll 1
        for (int k = 0; k < 8; k++) {
            int m = wid * 8 + k;
            int r = bi + m;
            if (r >= N_NODES) continue;
            float acc2 = 0.f;
            size_t rowb = (size_t)r * N_NODES;
            #pragma unroll
            for (int nb = 0; nb < 4; nb++) {
                int cj = bj + nb * 32 + lane;
                float val = __fmul_rn(Cst[m * 133 + nb * 32 + lane], cjv[nb]);
                if (cj < N_NODES) out[rowb + cj] = val;
                acc2 = fmaf(val, wjv[nb], acc2);
            }
            acc2 = wredsum(acc2);
            if (lane == 0) atomicAdd(&g_t[r], (double)acc2);
        }
    }

    // Transposed emission (off-diagonal): out[bj+n][bi+m] = C[m][n]*colinv[bi+m]
    if (bib != bjb) {
        float civ[4], wv[4];
        #pragma unroll
        for (int mb = 0; mb < 4; mb++) {
            int ri = bi + mb * 32 + lane;
            civ[mb] = g_colinv[ri];
            wv[mb] = g_w2[ri];
        }
        #pragma unroll 1
        for (int k = 0; k < 8; k++) {
            int n = wid * 8 + k;
            int cg = bj + n;
            if (cg >= N_NODES) continue;
            float acc2 = 0.f;
            size_t rowb = (size_t)cg * N_NODES;
            #pragma unroll
            for (int mb = 0; mb < 4; mb++) {
                int ri = bi + mb * 32 + lane;
                float val = __fmul_rn(Cst[(mb * 32 + lane) * 133 + n], civ[mb]);
                if (ri < N_NODES) out[rowb + ri] = val;
                acc2 = fmaf(val, wv[mb], acc2);
            }
            acc2 = wredsum(acc2);
            if (lane == 0) atomicAdd(&g_t[cg], (double)acc2);
        }
    }
}

// ---------------- k_normf ----------------
__global__ void k_normf(float* __restrict__ outp) {
    int i = blockIdx.x * blockDim.x + threadIdx.x;
    if (i >= N_NODES) return;
    float t = (float)g_t[i];
    outp[i] = 1.0f / (1.0f + expf(-t));
}

// ---------------- launch ----------------
extern "C" void kernel_launch(void* const* d_in, const int* in_sizes, int n_in,
                              void* d_out, int out_size) {
    const float* x      = (const float*)d_in[0];
    const int*   y      = (const int*)d_in[1];
    const int*   mask   = (const int*)d_in[2];
    const int*   e_ppi  = (const int*)d_in[3];
    const int*   e_hom  = (const int*)d_in[4];
    const float* W1     = (const float*)d_in[5];
    const float* as1    = (const float*)d_in[6];
    const float* ad1    = (const float*)d_in[7];
    const float* b1     = (const float*)d_in[8];
    const float* gamma_ = (const float*)d_in[9];
    const float* beta_  = (const float*)d_in[10];
    const float* W2     = (const float*)d_in[11];
    const float* as2    = (const float*)d_in[12];
    const float* ad2    = (const float*)d_in[13];
    const float* b2     = (const float*)d_in[14];
    const float* emb_w  = (const float*)d_in[15];
    const float* logitp = (const float*)d_in[16];
    float* out = (float*)d_out;

    const size_t OFF_NORM  = (size_t)N_NODES + 1;
    const size_t OFF_GRAPH = (size_t)2 * N_NODES + 1;
    const size_t OFF_PW    = OFF_GRAPH + (size_t)N_NODES * N_NODES;

    cudaFuncSetAttribute(k_graph_mma, cudaFuncAttributeMaxDynamicSharedMemorySize, SMEM_MMA);

    k_init<<<1, 128>>>(logitp, emb_w, out + OFF_PW);
    k_prep<<<(G_CNT * F_DIM * 32 + 255) / 256, 256>>>(W1);
    k_ex<<<NPAD / 8, 256>>>(x, mask);
    k_colinv<<<NPAD / 8, 256>>>(x);

    dim3 eg((E_EDGES + 255) / 256, 2);
    k_csr_hist<<<eg, 256>>>(e_ppi, e_hom);
    k_csr_scan<<<1, 1024>>>();
    k_csr_scatter<<<eg, 256>>>(e_ppi, e_hom);

    k_h1_all<<<313, 256>>>(x, as1, ad1);

    dim3 gg1(1250, G_CNT);
    k_gat1_all<<<gg1, 256>>>(b1, gamma_, beta_, W2, as2, ad2);
    k_gat2_all<<<gg1, 256>>>(b2, y, mask);

    k_nodep<<<(NPAD + 255) / 256, 256>>>(out);
    dim3 ggr(79, 79);
    k_graph_mma<<<ggr, 512, SMEM_MMA>>>(out + OFF_GRAPH);
    k_normf<<<(N_NODES + 255) / 256, 256>>>(out + OFF_NORM);
}

// round 14
// speedup vs baseline: 2.6749x; 1.2518x over previous
#include <cuda_runtime.h>
#include <cuda_fp16.h>
#include <cstdint>
#include <math.h>

#define N_NODES 10000
#define F_DIM   128
#define H_DIM   64
#define C_DIM   2
#define G_CNT   4
#define E_EDGES 320000
#define NPAD    10112                  // 79 * 128

// ---------------- scratch (device globals; no dynamic alloc) ----------------
__device__ float  g_kf[F_DIM];
__device__ float  g_ex[(size_t)NPAD * F_DIM];
__device__ __align__(16) __half g_exs[2][(size_t)NPAD * F_DIM];  // fp16 hi/lo splits
__device__ float  g_colinv[NPAD];
__device__ float2 g_W1p[G_CNT * F_DIM * 32];               // packed (c, c+32) pairs
__device__ float2 g_h1p[(size_t)G_CNT * N_NODES * 32];     // packed h1
__device__ float  g_al4[G_CNT * N_NODES], g_ar4[G_CNT * N_NODES];
__device__ float  g_al2a[G_CNT * N_NODES], g_ar2a[G_CNT * N_NODES];
__device__ float2 g_h2a[G_CNT * N_NODES];
__device__ float  g_oacc[G_CNT][N_NODES];
__device__ int    g_cnt[2][NPAD];
__device__ int    g_off[2][NPAD];
__device__ int    g_cur[2][NPAD];
__device__ int    g_csr[2][E_EDGES];
__device__ float  g_w2[NPAD];            // 2p-1 (zero padded)
__device__ double g_t[N_NODES];          // row accumulators for norm
__device__ float  g_loss[1];
__device__ float  g_masksum[1];

// ---------------- helpers ----------------
__device__ __forceinline__ float wredsum(float v) {
    #pragma unroll
    for (int o = 16; o > 0; o >>= 1) v += __shfl_xor_sync(0xffffffffu, v, o);
    return v;
}
__device__ __forceinline__ float sigmoidf_(float x) { return 1.0f / (1.0f + expf(-x)); }
__device__ __forceinline__ uint32_t smem_to_u32(const void* smem_ptr) {
    uint32_t addr;
    asm("{ .reg .u64 tmp; cvta.to.shared.u64 tmp, %1; cvt.u32.u64 %0, tmp; }"
        : "=r"(addr) : "l"(smem_ptr));
    return addr;
}

#define LDMATRIX_X4(r0, r1, r2, r3, addr) \
    asm volatile("ldmatrix.sync.aligned.m8n8.x4.shared.b16 {%0,%1,%2,%3}, [%4];" \
        : "=r"(r0), "=r"(r1), "=r"(r2), "=r"(r3) : "r"(addr))
#define LDMATRIX_X2(r0, r1, addr) \
    asm volatile("ldmatrix.sync.aligned.m8n8.x2.shared.b16 {%0,%1}, [%2];" \
        : "=r"(r0), "=r"(r1) : "r"(addr))
#define MMA16816F16(d, a, b) \
    asm volatile("mma.sync.aligned.m16n8k16.row.col.f32.f16.f16.f32 " \
        "{%0,%1,%2,%3}, {%4,%5,%6,%7}, {%8,%9}, {%0,%1,%2,%3};" \
        : "+f"((d)[0]), "+f"((d)[1]), "+f"((d)[2]), "+f"((d)[3]) \
        : "r"((a)[0]), "r"((a)[1]), "r"((a)[2]), "r"((a)[3]), "r"((b)[0]), "r"((b)[1]))

// ---------------- k_init ----------------
__global__ void k_init(const float* __restrict__ logit_p,
                       const float* __restrict__ emb_w,
                       float* __restrict__ pw_out) {
    int f = threadIdx.x;
    if (f < F_DIM) {
        float p = sigmoidf_(logit_p[f]);
        pw_out[f] = 1.0f - p;
        const float EPSf = 2.2204460492503131e-16f;
        float approx = logf(p + EPSf) - logf(1.0f - p + EPSf);
        float keep = 1.0f - sigmoidf_(approx * 10.0f);
        g_kf[f] = keep * sigmoidf_(emb_w[f]);
        if (f == 0) { g_loss[0] = 0.0f; g_masksum[0] = 0.0f; }
    }
}

// ---------------- k_prep: pack W1 ----------------
__global__ void k_prep(const float* __restrict__ W1) {
    int idx = blockIdx.x * 256 + threadIdx.x;
    if (idx >= G_CNT * F_DIM * 32) return;
    int lane = idx & 31;
    int k = (idx >> 5) & 127;
    int g = idx >> 12;
    const float* Wg = W1 + g * F_DIM * H_DIM + k * H_DIM;
    g_W1p[idx] = make_float2(Wg[lane], Wg[lane + 32]);
}

// ---------------- k_ex: ex = x*kf (exact), fp16x2 split fused, masksum ----------------
__global__ void k_ex(const float* __restrict__ x, const int* __restrict__ mask) {
    int w = blockIdx.x * 8 + (threadIdx.x >> 5);
    if (w >= NPAD) return;
    int lane = threadIdx.x & 31;
    size_t base = (size_t)w * F_DIM + lane * 4;
    float4 e = make_float4(0.f, 0.f, 0.f, 0.f);
    if (w < N_NODES) {
        float4 kf = *(const float4*)&g_kf[lane * 4];
        float4 xv = *(const float4*)&x[base];
        e.x = __fmul_rn(xv.x, kf.x); e.y = __fmul_rn(xv.y, kf.y);
        e.z = __fmul_rn(xv.z, kf.z); e.w = __fmul_rn(xv.w, kf.w);
        if (lane == 0 && mask[w] > 0) atomicAdd(&g_masksum[0], 1.0f);
    }
    *(float4*)&g_ex[base] = e;
    // fp16 2-way split (fused): e = h + m, |m| <= 2^-11 |e|
    const float* ep = (const float*)&e;
    __half hs[4], ms[4];
    #pragma unroll
    for (int q = 0; q < 4; q++) {
        float v = ep[q];
        __half h = __float2half_rn(v);
        float r = v - __half2float(h);
        hs[q] = h;
        ms[q] = __float2half_rn(r);
    }
    *(uint2*)&g_exs[0][base] = *(uint2*)hs;
    *(uint2*)&g_exs[1][base] = *(uint2*)ms;
    if (lane == 1) { g_cnt[0][w] = 0; g_cnt[1][w] = 0; }
}

// ---------------- k_colinv: SACRED — matched reference emitter order; do not touch ----------------
__global__ void k_colinv(const float* __restrict__ x) {
    int w = blockIdx.x * 8 + (threadIdx.x >> 5);
    if (w >= NPAD) return;
    int lane = threadIdx.x & 31;
    if (w < N_NODES) {
        const float* xr = x + (size_t)w * F_DIM;
        float2 xa = *(const float2*)&xr[2 * lane];
        float2 xb = *(const float2*)&xr[2 * lane + 64];
        float2 ka = *(const float2*)&g_kf[2 * lane];
        float2 kb = *(const float2*)&g_kf[2 * lane + 64];
        float i0 = __fadd_rn(__fmul_rn(xa.x, ka.x), __fmul_rn(xa.y, ka.y));
        float i1 = __fadd_rn(__fmul_rn(xb.x, kb.x), __fmul_rn(xb.y, kb.y));
        float s = __fadd_rn(i0, i1);
        s = wredsum(s);
        if (lane == 0) g_colinv[w] = __fdiv_rn(1.0f, __fadd_rn(s, 1e-6f));
    } else if (lane == 0) {
        g_colinv[w] = 0.0f;
    }
}

// ---------------- CSR build ----------------
__global__ void k_csr_hist(const int* __restrict__ e0, const int* __restrict__ e1) {
    int idx = blockIdx.x * 256 + threadIdx.x;
    if (idx >= E_EDGES) return;
    const int* ei = blockIdx.y ? e1 : e0;
    atomicAdd(&g_cnt[blockIdx.y][ei[E_EDGES + idx]], 1);
}

__global__ void k_csr_scan() {
    __shared__ int part[1024];
    int t = threadIdx.x;
    for (int list = 0; list < 2; list++) {
        const int chunk = 10;
        int base = t * chunk;
        int sum = 0;
        #pragma unroll
        for (int i = 0; i < chunk; i++) {
            int idx = base + i;
            if (idx < N_NODES) sum += g_cnt[list][idx];
        }
        part[t] = sum;
        __syncthreads();
        for (int off = 1; off < 1024; off <<= 1) {
            int u = (t >= off) ? part[t - off] : 0;
            __syncthreads();
            part[t] += u;
            __syncthreads();
        }
        int run = part[t] - sum;
        for (int i = 0; i < chunk; i++) {
            int idx = base + i;
            if (idx < N_NODES) {
                g_off[list][idx] = run;
                g_cur[list][idx] = run;
                run += g_cnt[list][idx];
            }
        }
        __syncthreads();
    }
}

__global__ void k_csr_scatter(const int* __restrict__ e0, const int* __restrict__ e1) {
    int idx = blockIdx.x * 256 + threadIdx.x;
    if (idx >= E_EDGES) return;
    int list = blockIdx.y;
    const int* ei = list ? e1 : e0;
    int s = ei[idx], d = ei[E_EDGES + idx];
    int pos = atomicAdd(&g_cur[list][d], 1);
    g_csr[list][pos] = s;
}

// ---------------- k_h1_all ----------------
__global__ __launch_bounds__(256) void k_h1_all(const float* __restrict__ x,
                                                const float* __restrict__ as1,
                                                const float* __restrict__ ad1) {
    int warp = blockIdx.x * 8 + (threadIdx.x >> 5);
    int lane = threadIdx.x & 31;
    if (warp >= 2500) return;
    int n0 = warp * 4;

    unsigned long long acc[4][4];
    #pragma unroll
    for (int g = 0; g < 4; g++)
        #pragma unroll
        for (int nd = 0; nd < 4; nd++) acc[g][nd] = 0ull;

    const float* xr = x + (size_t)n0 * F_DIM;
    for (int k = 0; k < F_DIM; k++) {
        unsigned long long xd[4];
        #pragma unroll
        for (int nd = 0; nd < 4; nd++) {
            unsigned xu = __float_as_uint(__ldg(xr + nd * F_DIM + k));
            asm("mov.b64 %0, {%1, %1};" : "=l"(xd[nd]) : "r"(xu));
        }
        #pragma unroll
        for (int g = 0; g < 4; g++) {
            float2 wv = g_W1p[(g * F_DIM + k) * 32 + lane];
            unsigned long long wd = *reinterpret_cast<unsigned long long*>(&wv);
            #pragma unroll
            for (int nd = 0; nd < 4; nd++)
                asm("fma.rn.f32x2 %0, %1, %2, %0;"
                    : "+l"(acc[g][nd]) : "l"(xd[nd]), "l"(wd));
        }
    }
    #pragma unroll
    for (int g = 0; g < 4; g++) {
        float asl = as1[g * 64 + lane], ash = as1[g * 64 + lane + 32];
        float adl = ad1[g * 64 + lane], adh = ad1[g * 64 + lane + 32];
        #pragma unroll
        for (int nd = 0; nd < 4; nd++) {
            unsigned long long v = acc[g][nd];
            float lo = __uint_as_float((unsigned)(v & 0xffffffffull));
            float hi = __uint_as_float((unsigned)(v >> 32));
            g_h1p[((size_t)g * N_NODES + n0 + nd) * 32 + lane] = make_float2(lo, hi);
            float ap = wredsum(lo * asl + hi * ash);
            float rp = wredsum(lo * adl + hi * adh);
            if (lane == 0) {
                g_al4[g * N_NODES + n0 + nd] = ap;
                g_ar4[g * N_NODES + n0 + nd] = rp;
            }
        }
    }
}

// ---------------- k_gat1_all ----------------
__global__ void k_gat1_all(const float* __restrict__ b1, const float* __restrict__ gm,
                           const float* __restrict__ bt, const float* __restrict__ W2,
                           const float* __restrict__ as2, const float* __restrict__ ad2) {
    int g = blockIdx.y, list = g & 1;
    int d = blockIdx.x * 8 + (threadIdx.x >> 5);
    if (d >= N_NODES) return;
    int lane = threadIdx.x & 31;

    const float* al = g_al4 + g * N_NODES;
    float ard = g_ar4[g * N_NODES + d];
    const float2* h1p = g_h1p + (size_t)g * N_NODES * 32;

    float a0 = al[d] + ard; a0 = (a0 >= 0.f) ? a0 : 0.2f * a0;
    float ee = expf(a0);
    float2 hd = h1p[d * 32 + lane];
    float accx = ee * hd.x, accy = ee * hd.y, s = ee;

    int k1 = g_off[list][d] + g_cnt[list][d];
    for (int k = g_off[list][d]; k < k1; k++) {
        int src = g_csr[list][k];
        float a = al[src] + ard; a = (a >= 0.f) ? a : 0.2f * a;
        float e = expf(a);
        float2 h = h1p[src * 32 + lane];
        s += e;
        accx = fmaf(e, h.x, accx);
        accy = fmaf(e, h.y, accy);
    }
    float inv = 1.0f / (s + 1e-16f);
    float h0  = accx * inv + b1[g * 64 + lane];
    float h1v = accy * inv + b1[g * 64 + lane + 32];
    const float BNS = 0.9999950000374997f;
    h0  = h0  * gm[g * 64 + lane]      * BNS + bt[g * 64 + lane];
    h1v = h1v * gm[g * 64 + lane + 32] * BNS + bt[g * 64 + lane + 32];
    h0  = (h0  >= 0.f) ? h0  : 0.01f * h0;
    h1v = (h1v >= 0.f) ? h1v : 0.01f * h1v;
    const float* W2g = W2 + g * H_DIM * C_DIM;
    float p0 = wredsum(h0 * W2g[lane * 2]     + h1v * W2g[(lane + 32) * 2]);
    float p1 = wredsum(h0 * W2g[lane * 2 + 1] + h1v * W2g[(lane + 32) * 2 + 1]);
    if (lane == 0) {
        g_h2a[g * N_NODES + d] = make_float2(p0, p1);
        g_al2a[g * N_NODES + d] = p0 * as2[g * 2] + p1 * as2[g * 2 + 1];
        g_ar2a[g * N_NODES + d] = p0 * ad2[g * 2] + p1 * ad2[g * 2 + 1];
    }
}

// ---------------- k_gat2_all ----------------
__global__ void k_gat2_all(const float* __restrict__ b2, const int* __restrict__ y,
                           const int* __restrict__ mask) {
    int g = blockIdx.y, list = g & 1;
    int d = blockIdx.x * 8 + (threadIdx.x >> 5);
    if (d >= N_NODES) return;
    int lane = threadIdx.x & 31;

    const float* al2 = g_al2a + g * N_NODES;
    float ar2d = g_ar2a[g * N_NODES + d];
    const float2* h2 = g_h2a + g * N_NODES;

    float s = 0.f, o0 = 0.f, o1 = 0.f;
    int k0 = g_off[list][d], k1 = k0 + g_cnt[list][d];
    for (int k = k0 + lane; k < k1; k += 32) {
        int src = g_csr[list][k];
        float a = al2[src] + ar2d; a = (a >= 0.f) ? a : 0.2f * a;
        float e = expf(a);
        float2 h = h2[src];
        s += e;
        o0 = fmaf(e, h.x, o0);
        o1 = fmaf(e, h.y, o1);
    }
    s = wredsum(s); o0 = wredsum(o0); o1 = wredsum(o1);
    if (lane == 0) {
        float a = al2[d] + ar2d; a = (a >= 0.f) ? a : 0.2f * a;
        float es = expf(a);
        float2 hd = h2[d];
        s += es; o0 += es * hd.x; o1 += es * hd.y;
        float inv = 1.0f / (s + 1e-16f);
        float v0 = o0 * inv + b2[g * 2];
        float v1 = o1 * inv + b2[g * 2 + 1];
        float mx = fmaxf(v0, v1);
        float lse = mx + logf(expf(v0 - mx) + expf(v1 - mx));
        float lp0 = v0 - lse, lp1 = v1 - lse;
        g_oacc[g][d] = expf(lp1);
        if (mask[d] > 0) atomicAdd(&g_loss[0], (y[d] == 0) ? lp0 : lp1);
    }
}

// ---------------- k_nodep ----------------
__global__ void k_nodep(float* __restrict__ dout) {
    int i = blockIdx.x * blockDim.x + threadIdx.x;
    if (i < NPAD) {
        if (i < N_NODES) {
            float p = (((g_oacc[0][i] + g_oacc[1][i]) + g_oacc[2][i]) + g_oacc[3][i]) * 0.25f;
            dout[i] = p;
            g_w2[i] = 2.0f * p - 1.0f;
            g_t[i] = 0.0;
        } else {
            g_w2[i] = 0.0f;
        }
    }
    if (i == 0) dout[N_NODES] = -g_loss[0] / (g_masksum[0] * (float)G_CNT);
}

// ---------------- k_graph_mma: mma.sync fp16x2 GEMM (3 passes), 512 thr, triangular, fused t ----------------
#define TSTRIDE   272
#define TILE_B    (128 * TSTRIDE)          // 34816
#define SMEM_MMA  (1024 + 4 * TILE_B)      // 140288

__global__ __launch_bounds__(512, 1) void k_graph_mma(float* __restrict__ out) {
    extern __shared__ char smem[];
    int bib = blockIdx.y, bjb = blockIdx.x;
    if (bjb < bib) return;
    int bi = bib * 128, bj = bjb * 128;
    int tid = threadIdx.x;
    int wid = tid >> 5, lane = tid & 31;
    uint32_t tbase = smem_to_u32(smem) + 1024;

    // Fill 4 tiles: q0=A_h q1=A_m (rows bi..), q2=B_h q3=B_m (rows bj..)
    #pragma unroll 1
    for (int q = 0; q < 4; q++) {
        int s = q & 1;
        int base_row = (q < 2) ? bi : bj;
        char* dst = smem + 1024 + q * TILE_B;
        const __half* src = g_exs[s] + (size_t)base_row * F_DIM;
        #pragma unroll
        for (int it = 0; it < 4; it++) {
            int t = it * 512 + tid;            // 0..2047
            int row = t >> 4, ch = t & 15;
            uint4 v = *(const uint4*)&src[(size_t)row * F_DIM + ch * 8];
            *(uint4*)(dst + row * TSTRIDE + ch * 16) = v;
        }
    }
    __syncthreads();

    // Warp layout: 4 (M) x 4 (N); warp tile 32x32
    int mw = wid & 3, nw = wid >> 2;
    float acc[2][4][4];
    #pragma unroll
    for (int mf = 0; mf < 2; mf++)
        #pragma unroll
        for (int nf = 0; nf < 4; nf++)
            #pragma unroll
            for (int r = 0; r < 4; r++) acc[mf][nf][r] = 0.f;

    int rowA = mw * 32 + (lane & 15);
    int kselA = ((lane >> 4) << 3);           // 0 or 8
    int rowB = nw * 32 + (lane & 7);
    int kselB = (lane & 8);                   // 0 or 8

    #pragma unroll 1
    for (int ks = 0; ks < 8; ks++) {
        int kb = ks * 16;
        // hoist all frags for this k-step into registers
        uint32_t ah[2][4], am[2][4];
        uint32_t ah_base = tbase + (kb + kselA) * 2;
        uint32_t am_base = tbase + TILE_B + (kb + kselA) * 2;
        #pragma unroll
        for (int mf = 0; mf < 2; mf++) {
            uint32_t ro = (rowA + mf * 16) * TSTRIDE;
            LDMATRIX_X4(ah[mf][0], ah[mf][1], ah[mf][2], ah[mf][3], ah_base + ro);
            LDMATRIX_X4(am[mf][0], am[mf][1], am[mf][2], am[mf][3], am_base + ro);
        }
        uint32_t bh[4][2], bm[4][2];
        uint32_t bh_base = tbase + 2 * TILE_B + (kb + kselB) * 2;
        uint32_t bm_base = tbase + 3 * TILE_B + (kb + kselB) * 2;
        #pragma unroll
        for (int nf = 0; nf < 4; nf++) {
            uint32_t ro = (rowB + nf * 8) * TSTRIDE;
            LDMATRIX_X2(bh[nf][0], bh[nf][1], bh_base + ro);
            LDMATRIX_X2(bm[nf][0], bm[nf][1], bm_base + ro);
        }
        // 3 passes: hh, hm, mh
        #pragma unroll
        for (int mf = 0; mf < 2; mf++)
            #pragma unroll
            for (int nf = 0; nf < 4; nf++) {
                MMA16816F16(acc[mf][nf], ah[mf], bh[nf]);
                MMA16816F16(acc[mf][nf], ah[mf], bm[nf]);
                MMA16816F16(acc[mf][nf], am[mf], bh[nf]);
            }
    }
    __syncthreads();   // all warps done reading tiles; reuse smem as Cst

    float* Cst = (float*)(smem + 1024);
    {
        int qr = lane >> 2;            // 0..7
        int qc = (lane & 3) * 2;       // 0,2,4,6
        #pragma unroll
        for (int mf = 0; mf < 2; mf++) {
            int m = mw * 32 + mf * 16 + qr;
            #pragma unroll
            for (int nf = 0; nf < 4; nf++) {
                int n = nw * 32 + nf * 8 + qc;
                Cst[m * 133 + n]           = acc[mf][nf][0];
                Cst[m * 133 + n + 1]       = acc[mf][nf][1];
                Cst[(m + 8) * 133 + n]     = acc[mf][nf][2];
                Cst[(m + 8) * 133 + n + 1] = acc[mf][nf][3];
            }
        }
    }
    __syncthreads();

    // Direct emission: out[bi+m][bj+n] = C[m][n]*colinv[bj+n]; t[bi+m] += val*w2
    {
        float cjv[4], wjv[4];
        #pragma unroll
        for (int nb = 0; nb < 4; nb++) {
            int cj = bj + nb * 32 + lane;
            cjv[nb] = g_colinv[cj];
            wjv[nb] = g_w2[cj];
        }
        #pragma unroll 1
        for (int k = 0; k < 8; k++) {
            int m = wid * 8 + k;
            int r = bi + m;
            if (r >= N_NODES) continue;
            float acc2 = 0.f;
            size_t rowb = (size_t)r * N_NODES;
            #pragma unroll
            for (int nb = 0; nb < 4; nb++) {
                int cj = bj + nb * 32 + lane;
                float val = __fmul_rn(Cst[m * 133 + nb * 32 + lane], cjv[nb]);
                if (cj < N_NODES) out[rowb + cj] = val;
                acc2 = fmaf(val, wjv[nb], acc2);
            }
            acc2 = wredsum(acc2);
            if (lane == 0) atomicAdd(&g_t[r], (double)acc2);
        }
    }

    // Transposed emission (off-diagonal): out[bj+n][bi+m] = C[m][n]*colinv[bi+m]
    if (bib != bjb) {
        float civ[4], wv[4];
        #pragma unroll
        for (int mb = 0; mb < 4; mb++) {
            int ri = bi + mb * 32 + lane;
            civ[mb] = g_colinv[ri];
            wv[mb] = g_w2[ri];
        }
        #pragma unroll 1
        for (int k = 0; k < 8; k++) {
            int n = wid * 8 + k;
            int cg = bj + n;
            if (cg >= N_NODES) continue;
            float acc2 = 0.f;
            size_t rowb = (size_t)cg * N_NODES;
            #pragma unroll
            for (int mb = 0; mb < 4; mb++) {
                int ri = bi + mb * 32 + lane;
                float val = __fmul_rn(Cst[(mb * 32 + lane) * 133 + n], civ[mb]);
                if (ri < N_NODES) out[rowb + ri] = val;
                acc2 = fmaf(val, wv[mb], acc2);
            }
            acc2 = wredsum(acc2);
            if (lane == 0) atomicAdd(&g_t[cg], (double)acc2);
        }
    }
}

// ---------------- k_normf ----------------
__global__ void k_normf(float* __restrict__ outp) {
    int i = blockIdx.x * blockDim.x + threadIdx.x;
    if (i >= N_NODES) return;
    float t = (float)g_t[i];
    outp[i] = 1.0f / (1.0f + expf(-t));
}

// ---------------- launch ----------------
extern "C" void kernel_launch(void* const* d_in, const int* in_sizes, int n_in,
                              void* d_out, int out_size) {
    const float* x      = (const float*)d_in[0];
    const int*   y      = (const int*)d_in[1];
    const int*   mask   = (const int*)d_in[2];
    const int*   e_ppi  = (const int*)d_in[3];
    const int*   e_hom  = (const int*)d_in[4];
    const float* W1     = (const float*)d_in[5];
    const float* as1    = (const float*)d_in[6];
    const float* ad1    = (const float*)d_in[7];
    const float* b1     = (const float*)d_in[8];
    const float* gamma_ = (const float*)d_in[9];
    const float* beta_  = (const float*)d_in[10];
    const float* W2     = (const float*)d_in[11];
    const float* as2    = (const float*)d_in[12];
    const float* ad2    = (const float*)d_in[13];
    const float* b2     = (const float*)d_in[14];
    const float* emb_w  = (const float*)d_in[15];
    const float* logitp = (const float*)d_in[16];
    float* out = (float*)d_out;

    const size_t OFF_NORM  = (size_t)N_NODES + 1;
    const size_t OFF_GRAPH = (size_t)2 * N_NODES + 1;
    const size_t OFF_PW    = OFF_GRAPH + (size_t)N_NODES * N_NODES;

    cudaFuncSetAttribute(k_graph_mma, cudaFuncAttributeMaxDynamicSharedMemorySize, SMEM_MMA);

    k_init<<<1, 128>>>(logitp, emb_w, out + OFF_PW);
    k_prep<<<(G_CNT * F_DIM * 32 + 255) / 256, 256>>>(W1);
    k_ex<<<NPAD / 8, 256>>>(x, mask);
    k_colinv<<<NPAD / 8, 256>>>(x);

    dim3 eg((E_EDGES + 255) / 256, 2);
    k_csr_hist<<<eg, 256>>>(e_ppi, e_hom);
    k_csr_scan<<<1, 1024>>>();
    k_csr_scatter<<<eg, 256>>>(e_ppi, e_hom);

    k_h1_all<<<313, 256>>>(x, as1, ad1);

    dim3 gg1(1250, G_CNT);
    k_gat1_all<<<gg1, 256>>>(b1, gamma_, beta_, W2, as2, ad2);
    k_gat2_all<<<gg1, 256>>>(b2, y, mask);

    k_nodep<<<(NPAD + 255) / 256, 256>>>(out);
    dim3 ggr(79, 79);
    k_graph_mma<<<ggr, 512, SMEM_MMA>>>(out + OFF_GRAPH);
    k_normf<<<(N_NODES + 255) / 256, 256>>>(out + OFF_NORM);
}